// round 12
// baseline (speedup 1.0000x reference)
#include <cuda_runtime.h>
#include <cuda_bf16.h>
#include <cuda_fp16.h>
#include <cstdint>

#define B_   2
#define S_   2048
#define D_   1024
#define H_   16
#define DK_  64
#define BH_  (B_ * H_)
#define M_ROWS (B_ * S_)   // 4096

#define QSCALE 0.18033688011112042f   // log2(e)/sqrt(64)

// ---------------- scratch ----------------
__device__ __half g_Xhi[M_ROWS * D_];
__device__ __half g_Xlo[M_ROWS * D_];
__device__ __half g_Wth[4 * D_ * D_];
__device__ __half g_Wtl[4 * D_ * D_];
__device__ __nv_bfloat16 g_Qh[BH_ * S_ * DK_];
__device__ __nv_bfloat16 g_Ql[BH_ * S_ * DK_];
__device__ __nv_bfloat16 g_Kh[BH_ * S_ * DK_];
__device__ __nv_bfloat16 g_Kl[BH_ * S_ * DK_];
__device__ __nv_bfloat16 g_Vh[BH_ * S_ * DK_];
__device__ __nv_bfloat16 g_Vl[BH_ * S_ * DK_];

// ---------------- helpers ----------------
__device__ __forceinline__ uint32_t smem_u32(const void* p) {
    uint32_t a;
    asm("{ .reg .u64 t; cvta.to.shared.u64 t, %1; cvt.u32.u64 %0, t; }" : "=r"(a) : "l"(p));
    return a;
}
__device__ __forceinline__ void ldsm4(uint32_t* r, uint32_t addr) {
    asm volatile("ldmatrix.sync.aligned.m8n8.x4.shared.b16 {%0,%1,%2,%3}, [%4];"
        : "=r"(r[0]), "=r"(r[1]), "=r"(r[2]), "=r"(r[3]) : "r"(addr));
}
__device__ __forceinline__ void ldsm4t(uint32_t* r, uint32_t addr) {
    asm volatile("ldmatrix.sync.aligned.m8n8.x4.trans.shared.b16 {%0,%1,%2,%3}, [%4];"
        : "=r"(r[0]), "=r"(r[1]), "=r"(r[2]), "=r"(r[3]) : "r"(addr));
}
__device__ __forceinline__ void mma16816(float* c, const uint32_t* a, const uint32_t* b) {
    asm volatile("mma.sync.aligned.m16n8k16.row.col.f32.bf16.bf16.f32 "
        "{%0,%1,%2,%3}, {%4,%5,%6,%7}, {%8,%9}, {%0,%1,%2,%3};"
        : "+f"(c[0]), "+f"(c[1]), "+f"(c[2]), "+f"(c[3])
        : "r"(a[0]), "r"(a[1]), "r"(a[2]), "r"(a[3]), "r"(b[0]), "r"(b[1]));
}
__device__ __forceinline__ void mma16816h(float* c, const uint32_t* a, const uint32_t* b) {
    asm volatile("mma.sync.aligned.m16n8k16.row.col.f32.f16.f16.f32 "
        "{%0,%1,%2,%3}, {%4,%5,%6,%7}, {%8,%9}, {%0,%1,%2,%3};"
        : "+f"(c[0]), "+f"(c[1]), "+f"(c[2]), "+f"(c[3])
        : "r"(a[0]), "r"(a[1]), "r"(a[2]), "r"(a[3]), "r"(b[0]), "r"(b[1]));
}
__device__ __forceinline__ void mma16816hh(uint32_t* c, const uint32_t* a, const uint32_t* b) {
    asm volatile("mma.sync.aligned.m16n8k16.row.col.f16.f16.f16.f16 "
        "{%0,%1}, {%2,%3,%4,%5}, {%6,%7}, {%0,%1};"
        : "+r"(c[0]), "+r"(c[1])
        : "r"(a[0]), "r"(a[1]), "r"(a[2]), "r"(a[3]), "r"(b[0]), "r"(b[1]));
}
__device__ __forceinline__ void cpa16(uint32_t d, const void* g) {
    asm volatile("cp.async.cg.shared.global [%0], [%1], 16;" :: "r"(d), "l"(g));
}
#define CP_COMMIT() asm volatile("cp.async.commit_group;" ::: "memory")
#define CP_WAIT0()  asm volatile("cp.async.wait_group 0;" ::: "memory")
#define CP_WAIT1()  asm volatile("cp.async.wait_group 1;" ::: "memory")

__device__ __forceinline__ void split2(float a, float b, uint32_t& hi, uint32_t& lo) {
    uint32_t h;
    asm("cvt.rn.bf16x2.f32 %0, %1, %2;" : "=r"(h) : "f"(b), "f"(a));
    const float fa = __uint_as_float(h << 16);
    const float fb = __uint_as_float(h & 0xffff0000u);
    const float ra = a - fa, rb = b - fb;
    uint32_t l;
    asm("cvt.rn.bf16x2.f32 %0, %1, %2;" : "=r"(l) : "f"(rb), "f"(ra));
    hi = h; lo = l;
}
__device__ __forceinline__ void split2h(float a, float b, uint32_t& hi, uint32_t& lo) {
    uint32_t h;
    asm("cvt.rn.f16x2.f32 %0, %1, %2;" : "=r"(h) : "f"(b), "f"(a));
    const __half2 hp = *(const __half2*)&h;
    const float fa = __half2float(__low2half(hp));
    const float fb = __half2float(__high2half(hp));
    const float ra = a - fa, rb = b - fb;
    uint32_t l;
    asm("cvt.rn.f16x2.f32 %0, %1, %2;" : "=r"(l) : "f"(rb), "f"(ra));
    hi = h; lo = l;
}

// ---------------------------------------------------------------------------
__global__ __launch_bounds__(256) void split_f16(
    const float* __restrict__ src, __half* __restrict__ hi,
    __half* __restrict__ lo, int n4)
{
    int i = blockIdx.x * blockDim.x + threadIdx.x;
    if (i >= n4) return;
    float4 v = ((const float4*)src)[i];
    uint32_t h0, l0, h1, l1;
    split2h(v.x, v.y, h0, l0);
    split2h(v.z, v.w, h1, l1);
    uint2 hu = {h0, h1}, lu = {l0, l1};
    ((uint2*)hi)[i] = hu;
    ((uint2*)lo)[i] = lu;
}

// ---------------------------------------------------------------------------
__global__ void transpose_split(const float* __restrict__ W0,
                                const float* __restrict__ W1,
                                const float* __restrict__ W2,
                                const float* __restrict__ W3,
                                __half* __restrict__ hi,
                                __half* __restrict__ lo)
{
    __shared__ float t[32][33];
    const float* W = (blockIdx.z == 0) ? W0 : (blockIdx.z == 1) ? W1 :
                     (blockIdx.z == 2) ? W2 : W3;
    const int k = blockIdx.y * 32 + threadIdx.y;
    const int n = blockIdx.x * 32 + threadIdx.x;
    t[threadIdx.y][threadIdx.x] = W[(size_t)k * D_ + n];
    __syncthreads();
    const int nn = blockIdx.x * 32 + threadIdx.y + blockIdx.z * D_;
    const int kk = blockIdx.y * 32 + threadIdx.x;
    float v = t[threadIdx.x][threadIdx.y];
    __half h = __float2half_rn(v);
    __half l = __float2half_rn(v - __half2float(h));
    hi[(size_t)nn * D_ + kk] = h;
    lo[(size_t)nn * D_ + kk] = l;
}

// ---------------------------------------------------------------------------
// HMMA GEMM (unchanged from R10/R11).
// ---------------------------------------------------------------------------
#define GROWB 80
#define SLABB (128 * GROWB)
#define STAGEB (4 * SLABB)
#define GSMEM (2 * STAGEB)

__global__ __launch_bounds__(256, 2) void gemm_tc(
    const __half* __restrict__ Ah, const __half* __restrict__ Al,
    const __half* __restrict__ Bh, const __half* __restrict__ Bl,
    const float* __restrict__ b0, const float* __restrict__ b1,
    const float* __restrict__ b2, float* __restrict__ Yf,
    __nv_bfloat16* __restrict__ Qh, __nv_bfloat16* __restrict__ Ql,
    __nv_bfloat16* __restrict__ Kh, __nv_bfloat16* __restrict__ Kl,
    __nv_bfloat16* __restrict__ Vh, __nv_bfloat16* __restrict__ Vl,
    int mode)
{
    extern __shared__ __align__(16) unsigned char dsm[];
    const uint32_t s0 = smem_u32(dsm);

    const int tid = threadIdx.x, wid = tid >> 5, lane = tid & 31;
    const int wm = wid >> 2, wn = wid & 3;
    const int bm = blockIdx.y * 128, bn = blockIdx.x * 128;

    const int a4 = tid >> 6, t4 = tid & 63;
    const __half* gsrc =
        (a4 == 0) ? Ah : (a4 == 1) ? Al : (a4 == 2) ? Bh : Bl;
    gsrc += (size_t)((a4 < 2) ? bm : bn) * 1024;
    const uint32_t slab = s0 + (uint32_t)a4 * SLABB;

    const uint32_t aRow = (uint32_t)(wm * 64 + (lane & 15));
    const uint32_t aCol = (uint32_t)(lane >> 4) * 16;
    const uint32_t bRow0 = (uint32_t)(wn * 32 + ((lane >> 4) & 1) * 8 + (lane & 7));
    const uint32_t bKoff = (uint32_t)((lane >> 3) & 1) * 16;

    float acc[16][4];
    uint32_t facc[16][2];
#pragma unroll
    for (int i = 0; i < 16; i++) {
#pragma unroll
        for (int j = 0; j < 4; j++) acc[i][j] = 0.f;
        facc[i][0] = 0u; facc[i][1] = 0u;
    }

    auto issue = [&](int ks) {
        const uint32_t st = slab + (uint32_t)(ks & 1) * STAGEB;
        const __half* g = gsrc + ks * 32;
#pragma unroll
        for (int p = 0; p < 8; p++) {
            const int idx = p * 64 + t4;
            const int row = idx >> 2, ch = idx & 3;
            cpa16(st + (uint32_t)row * GROWB + (uint32_t)ch * 16,
                  g + (size_t)row * 1024 + ch * 8);
        }
        CP_COMMIT();
    };

    issue(0);

    for (int ks = 0; ks < 32; ks++) {
        CP_WAIT0();
        __syncthreads();
        if (ks + 1 < 32) issue(ks + 1);

        const uint32_t sb  = s0 + (uint32_t)(ks & 1) * STAGEB;
        const uint32_t SAh = sb, SAl = sb + SLABB;
        const uint32_t SBh = sb + 2 * SLABB, SBl = sb + 3 * SLABB;

#pragma unroll
        for (int h = 0; h < 2; h++) {
            uint32_t fA[4][4], fB[4][2];
            const uint32_t hoff = (uint32_t)h * 32;
#pragma unroll
            for (int mt = 0; mt < 4; mt++)
                ldsm4(fA[mt], SAh + (aRow + (uint32_t)(mt * 16)) * GROWB + hoff + aCol);
#pragma unroll
            for (int g = 0; g < 2; g++) {
                uint32_t r[4];
                ldsm4(r, SBh + (bRow0 + (uint32_t)(g * 16)) * GROWB + hoff + bKoff);
                fB[g * 2][0] = r[0]; fB[g * 2][1] = r[1];
                fB[g * 2 + 1][0] = r[2]; fB[g * 2 + 1][1] = r[3];
            }
#pragma unroll
            for (int mt = 0; mt < 4; mt++)
#pragma unroll
                for (int nt = 0; nt < 4; nt++)
                    mma16816h(acc[mt * 4 + nt], fA[mt], fB[nt]);
#pragma unroll
            for (int mt = 0; mt < 4; mt++)
                ldsm4(fA[mt], SAl + (aRow + (uint32_t)(mt * 16)) * GROWB + hoff + aCol);
#pragma unroll
            for (int mt = 0; mt < 4; mt++)
#pragma unroll
                for (int nt = 0; nt < 4; nt++)
                    mma16816hh(facc[mt * 4 + nt], fA[mt], fB[nt]);
#pragma unroll
            for (int g = 0; g < 2; g++) {
                uint32_t r[4];
                ldsm4(r, SBl + (bRow0 + (uint32_t)(g * 16)) * GROWB + hoff + bKoff);
                fB[g * 2][0] = r[0]; fB[g * 2][1] = r[1];
                fB[g * 2 + 1][0] = r[2]; fB[g * 2 + 1][1] = r[3];
            }
#pragma unroll
            for (int mt = 0; mt < 4; mt++)
                ldsm4(fA[mt], SAh + (aRow + (uint32_t)(mt * 16)) * GROWB + hoff + aCol);
#pragma unroll
            for (int mt = 0; mt < 4; mt++)
#pragma unroll
                for (int nt = 0; nt < 4; nt++)
                    mma16816hh(facc[mt * 4 + nt], fA[mt], fB[nt]);
        }
    }

    const int qr = lane >> 2, qc = (lane & 3) * 2;
    const int proj = bn >> 10;
    const float* bias = (proj == 0) ? b0 : (proj == 1) ? b1 : b2;
    const float scale = (mode == 1 && proj == 0) ? QSCALE : 1.0f;
    __nv_bfloat16* Yh = (proj == 0) ? Qh : (proj == 1) ? Kh : Vh;
    __nv_bfloat16* Yl = (proj == 0) ? Ql : (proj == 1) ? Kl : Vl;
    const int bnl = bn & 1023;

#pragma unroll
    for (int mt = 0; mt < 4; mt++) {
#pragma unroll
        for (int nt = 0; nt < 4; nt++) {
            const int i = mt * 4 + nt;
            const __half2 c01 = *(const __half2*)&facc[i][0];
            const __half2 c23 = *(const __half2*)&facc[i][1];
            const float v0f = acc[i][0] + __half2float(__low2half(c01));
            const float v1f = acc[i][1] + __half2float(__high2half(c01));
            const float v2f = acc[i][2] + __half2float(__low2half(c23));
            const float v3f = acc[i][3] + __half2float(__high2half(c23));
            const int r0 = bm + wm * 64 + mt * 16 + qr;
            const int cn = bnl + wn * 32 + nt * 8 + qc;
            const float bv0 = bias[cn], bv1 = bias[cn + 1];
            if (mode == 0) {
                float2 v0 = {v0f + bv0, v1f + bv1};
                float2 v1 = {v2f + bv0, v3f + bv1};
                *(float2*)(Yf + (size_t)r0 * 1024 + cn) = v0;
                *(float2*)(Yf + (size_t)(r0 + 8) * 1024 + cn) = v1;
            } else {
                const float w0 = (v0f + bv0) * scale, w1 = (v1f + bv1) * scale;
                const float w2 = (v2f + bv0) * scale, w3 = (v3f + bv1) * scale;
                const int h  = cn >> 6, dk = cn & 63;
                const int b0i = r0 >> 11, s0i = r0 & 2047;
                const int b1i = (r0 + 8) >> 11, s1i = (r0 + 8) & 2047;
                const size_t o0 = (((size_t)(b0i * H_ + h)) * S_ + s0i) * DK_ + dk;
                const size_t o1 = (((size_t)(b1i * H_ + h)) * S_ + s1i) * DK_ + dk;
                uint32_t h0, l0, h1, l1;
                split2(w0, w1, h0, l0);
                split2(w2, w3, h1, l1);
                *(uint32_t*)(Yh + o0) = h0; *(uint32_t*)(Yl + o0) = l0;
                *(uint32_t*)(Yh + o1) = h1; *(uint32_t*)(Yl + o1) = l1;
            }
        }
    }
}

// ---------------------------------------------------------------------------
// Flash attention (causal): 128 thr / 64 q-rows, 2 CTAs/SM.
// R12: cross-tile pipeline — QK(j+1) issued BEFORE softmax/PV of tile j,
// 3-stage KV ring (prefetch distance 2). Tensor pipe keeps a backlog while
// the softmax scalars execute.
// smem: Q hi@0 lo@8192 (16K); stage s at 16384+ (s%3)*32768:
//   Kh+0, Kl+8192, Vh+16384, Vl+24576. Total 112K.
// ---------------------------------------------------------------------------
#define ASMEM 114688

__global__ __launch_bounds__(128, 2) void flash_attn_tc(
    const __nv_bfloat16* __restrict__ Qh, const __nv_bfloat16* __restrict__ Ql,
    const __nv_bfloat16* __restrict__ Kh, const __nv_bfloat16* __restrict__ Kl,
    const __nv_bfloat16* __restrict__ Vh, const __nv_bfloat16* __restrict__ Vl,
    __half* __restrict__ Ohi, __half* __restrict__ Olo)
{
    extern __shared__ __align__(16) unsigned char sm[];
    const uint32_t s0 = smem_u32(sm);

    const int tid = threadIdx.x, wid = tid >> 5, lane = tid & 31;
    const int qt = 31 - blockIdx.x;          // heavy tiles first
    const int bh = blockIdx.y;
    const int qbase = qt * 64;
    const int njt = qt + 1;
    const int rb = wid * 16;

    // ---- stage Q (hi@0, lo@8192) ----
    {
        const int arr = tid >> 6;
        const int t2 = tid & 63;
        const __nv_bfloat16* base = (arr ? Ql : Qh) + ((size_t)bh * S_ + qbase) * DK_;
        const uint32_t db = (uint32_t)arr * 8192;
#pragma unroll
        for (int p = 0; p < 8; p++) {
            const int idx = p * 64 + t2;
            const int row = idx >> 3, ch = idx & 7;
            *(uint4*)(sm + db + (uint32_t)row * 128 + (uint32_t)((ch ^ (row & 7)) << 4)) =
                *(const uint4*)(base + (size_t)row * 64 + ch * 8);
        }
    }

    // ---- KV copy geometry: one array per warp ----
    const int a4 = wid;                       // 0:Kh 1:Kl 2:Vh 3:Vl
    const int t5 = lane;
    const __nv_bfloat16* kvsrc =
        (a4 == 0) ? Kh : (a4 == 1) ? Kl : (a4 == 2) ? Vh : Vl;
    kvsrc += (size_t)bh * S_ * DK_;
    const uint32_t kvbase = s0 + 16384 + (uint32_t)a4 * 8192;

    auto prefetch = [&](int s) {
        const __nv_bfloat16* g = kvsrc + (size_t)s * 64 * 64;
        const uint32_t db = kvbase + (uint32_t)(s % 3) * 32768;
#pragma unroll
        for (int p = 0; p < 16; p++) {
            const int idx = p * 32 + t5;
            const int row = idx >> 3, ch = idx & 7;
            cpa16(db + (uint32_t)row * 128 + (uint32_t)((ch ^ (row & 7)) << 4),
                  g + (size_t)row * 64 + ch * 8);
        }
        CP_COMMIT();
    };

    prefetch(0);
    if (njt > 1) prefetch(1);
    if (njt > 1) { CP_WAIT1(); } else { CP_WAIT0(); }
    __syncthreads();    // Q staged + stage 0 visible to all warps

    // Q-hi fragments resident; Q-lo reloaded per use
    uint32_t qfh[4][4], qaddr[4];
    {
        const int row = rb + (lane & 15);
        const int r7 = row & 7;
#pragma unroll
        for (int kk = 0; kk < 4; kk++) {
            qaddr[kk] = s0 + (uint32_t)row * 128 +
                        (uint32_t)(((2 * kk + (lane >> 4)) ^ r7) << 4);
            ldsm4(qfh[kk], qaddr[kk]);
        }
    }

    float m_i[2] = {-1e30f, -1e30f};
    float l_i[2] = {0.f, 0.f};
    float oac[8][4];
#pragma unroll
    for (int t = 0; t < 8; t++)
#pragma unroll
        for (int e = 0; e < 4; e++) oac[t][e] = 0.f;

    float sca[8][4], scb[8][4];

    // QK for one tile: 96 MMAs + optional causal mask
    auto do_qk = [&](float (&sc)[8][4], uint32_t bb, bool domask) {
#pragma unroll
        for (int t = 0; t < 8; t++)
#pragma unroll
            for (int e = 0; e < 4; e++) sc[t][e] = 0.f;
#pragma unroll
        for (int kk = 0; kk < 4; kk++) {
            uint32_t qfl[4];
            ldsm4(qfl, qaddr[kk] + 8192);
#pragma unroll
            for (int j = 0; j < 4; j++) {
                const int krow = 16 * j + (lane & 7) + ((lane & 16) >> 1);
                const uint32_t ka = bb + (uint32_t)krow * 128 +
                    (uint32_t)(((2 * kk + ((lane >> 3) & 1)) ^ (krow & 7)) << 4);
                uint32_t bhf[4], blf[4];
                ldsm4(bhf, ka);
                ldsm4(blf, ka + 8192);
                mma16816(sc[2 * j],     qfh[kk], bhf + 0);
                mma16816(sc[2 * j + 1], qfh[kk], bhf + 2);
                mma16816(sc[2 * j],     qfh[kk], blf + 0);
                mma16816(sc[2 * j + 1], qfh[kk], blf + 2);
                mma16816(sc[2 * j],     qfl,     bhf + 0);
                mma16816(sc[2 * j + 1], qfl,     bhf + 2);
            }
        }
        if (domask) {
#pragma unroll
            for (int t = 0; t < 8; t++)
#pragma unroll
                for (int e = 0; e < 4; e++) {
                    const int kg = t * 8 + 2 * (lane & 3) + (e & 1);
                    const int qg = rb + (lane >> 2) + (e >> 1) * 8;
                    if (kg > qg) sc[t][e] = -1e9f;
                }
        }
    };

    // prologue: QK(0)
    do_qk(sca, s0 + 16384, njt == 1);

    for (int j = 0; j < njt; j++) {
        if (j + 1 < njt) CP_WAIT0();   // my quarter of stage j+1 done
        __syncthreads();               // cross-warp visibility + all done iter j-1
        if (j + 2 < njt) prefetch(j + 2);

        // QK(j+1) FIRST — independent MMA backlog before the scalars
        if (j + 1 < njt)
            do_qk(scb, s0 + 16384 + (uint32_t)((j + 1) % 3) * 32768,
                  (j + 1) == njt - 1);

        const uint32_t bbv = s0 + 16384 + (uint32_t)(j % 3) * 32768 + 16384;

        // softmax phase 1: max + exp2 (overlaps QK(j+1) drain)
        float mn[2];
#pragma unroll
        for (int h = 0; h < 2; h++) {
            float mr = -1e30f;
#pragma unroll
            for (int t = 0; t < 8; t++)
                mr = fmaxf(mr, fmaxf(sca[t][2 * h], sca[t][2 * h + 1]));
            mr = fmaxf(mr, __shfl_xor_sync(0xffffffffu, mr, 1));
            mr = fmaxf(mr, __shfl_xor_sync(0xffffffffu, mr, 2));
            mn[h] = fmaxf(m_i[h], mr);
#pragma unroll
            for (int t = 0; t < 8; t++) {
                sca[t][2 * h]     = exp2f(sca[t][2 * h] - mn[h]);
                sca[t][2 * h + 1] = exp2f(sca[t][2 * h + 1] - mn[h]);
            }
        }
        // rescale oac
#pragma unroll
        for (int h = 0; h < 2; h++) {
            const float alpha = exp2f(m_i[h] - mn[h]);
            m_i[h] = mn[h];
            l_i[h] *= alpha;
#pragma unroll
            for (int t = 0; t < 8; t++) {
                oac[t][2 * h]     *= alpha;
                oac[t][2 * h + 1] *= alpha;
            }
        }

        // PV into oac
#pragma unroll
        for (int kk = 0; kk < 4; kk++) {
            uint32_t pah[4], pal[4];
            split2(sca[2 * kk][0],     sca[2 * kk][1],     pah[0], pal[0]);
            split2(sca[2 * kk][2],     sca[2 * kk][3],     pah[1], pal[1]);
            split2(sca[2 * kk + 1][0], sca[2 * kk + 1][1], pah[2], pal[2]);
            split2(sca[2 * kk + 1][2], sca[2 * kk + 1][3], pah[3], pal[3]);

            const int vrow = 16 * kk + (lane & 15);
            const int vr7 = vrow & 7;
#pragma unroll
            for (int jj = 0; jj < 4; jj++) {
                const uint32_t va = bbv + (uint32_t)vrow * 128 +
                    (uint32_t)(((2 * jj + (lane >> 4)) ^ vr7) << 4);
                uint32_t vhf[4], vlf[4];
                ldsm4t(vhf, va);
                ldsm4t(vlf, va + 8192);
                mma16816(oac[2 * jj],     pah, vhf + 0);
                mma16816(oac[2 * jj + 1], pah, vhf + 2);
                mma16816(oac[2 * jj],     pah, vlf + 0);
                mma16816(oac[2 * jj + 1], pah, vlf + 2);
                mma16816(oac[2 * jj],     pal, vhf + 0);
                mma16816(oac[2 * jj + 1], pal, vhf + 2);
            }
        }

        // row-sum (overlaps PV drain)
#pragma unroll
        for (int h = 0; h < 2; h++) {
            float rs = 0.f;
#pragma unroll
            for (int t = 0; t < 8; t++)
                rs += sca[t][2 * h] + sca[t][2 * h + 1];
            rs += __shfl_xor_sync(0xffffffffu, rs, 1);
            rs += __shfl_xor_sync(0xffffffffu, rs, 2);
            l_i[h] += rs;
        }

        if (j + 1 < njt) {
#pragma unroll
            for (int t = 0; t < 8; t++)
#pragma unroll
                for (int e = 0; e < 4; e++) sca[t][e] = scb[t][e];
        }
    }

    // ---- epilogue: ctx fp16 hi/lo ----
    const int bb_ = bh >> 4, hh = bh & 15;
#pragma unroll
    for (int h = 0; h < 2; h++) {
        const float invl = 1.f / l_i[h];
        const int rg = qbase + rb + (lane >> 2) + 8 * h;
        const size_t mrow = (size_t)(bb_ * 2048 + rg) * 1024;
#pragma unroll
        for (int t = 0; t < 8; t++) {
            const float v0 = oac[t][2 * h] * invl;
            const float v1 = oac[t][2 * h + 1] * invl;
            const int col = hh * 64 + t * 8 + 2 * (lane & 3);
            uint32_t hi, lo;
            split2h(v0, v1, hi, lo);
            *(uint32_t*)(Ohi + mrow + col) = hi;
            *(uint32_t*)(Olo + mrow + col) = lo;
        }
    }
}

// ---------------------------------------------------------------------------
extern "C" void kernel_launch(void* const* d_in, const int* in_sizes, int n_in,
                              void* d_out, int out_size)
{
    const float* x  = (const float*)d_in[0];
    const float* Wq = (const float*)d_in[2];
    const float* bq = (const float*)d_in[3];
    const float* Wk = (const float*)d_in[4];
    const float* bk = (const float*)d_in[5];
    const float* Wv = (const float*)d_in[6];
    const float* bv = (const float*)d_in[7];
    const float* Wo = (const float*)d_in[8];
    const float* bo = (const float*)d_in[9];

    __half *xh, *xl, *wth, *wtl;
    __nv_bfloat16 *qh, *ql, *kh, *kl, *vh, *vl;
    cudaGetSymbolAddress((void**)&xh, g_Xhi);
    cudaGetSymbolAddress((void**)&xl, g_Xlo);
    cudaGetSymbolAddress((void**)&wth, g_Wth);
    cudaGetSymbolAddress((void**)&wtl, g_Wtl);
    cudaGetSymbolAddress((void**)&qh, g_Qh);
    cudaGetSymbolAddress((void**)&ql, g_Ql);
    cudaGetSymbolAddress((void**)&kh, g_Kh);
    cudaGetSymbolAddress((void**)&kl, g_Kl);
    cudaGetSymbolAddress((void**)&vh, g_Vh);
    cudaGetSymbolAddress((void**)&vl, g_Vl);

    const int n4 = M_ROWS * D_ / 4;
    const dim3 tb(32, 32);

    cudaFuncSetAttribute(gemm_tc, cudaFuncAttributeMaxDynamicSharedMemorySize, GSMEM);
    cudaFuncSetAttribute(flash_attn_tc, cudaFuncAttributeMaxDynamicSharedMemorySize, ASMEM);

    split_f16<<<(n4 + 255) / 256, 256>>>(x, xh, xl, n4);
    // all four weight transposes in one launch (Wo slice at z=3)
    transpose_split<<<dim3(32, 32, 4), tb>>>(Wq, Wk, Wv, Wo, wth, wtl);

    gemm_tc<<<dim3(24, 32), 256, GSMEM>>>(xh, xl, wth, wtl, bq, bk, bv,
                                          nullptr, qh, ql, kh, kl, vh, vl, 1);

    flash_attn_tc<<<dim3(32, BH_), 128, ASMEM>>>(qh, ql, kh, kl, vh, vl, xh, xl);

    gemm_tc<<<dim3(8, 32), 256, GSMEM>>>(xh, xl, wth + 3 * D_ * D_, wtl + 3 * D_ * D_,
                                         bo, bo, bo, (float*)d_out,
                                         nullptr, nullptr, nullptr, nullptr,
                                         nullptr, nullptr, 0);
}

// round 13
// speedup vs baseline: 1.1462x; 1.1462x over previous
#include <cuda_runtime.h>
#include <cuda_bf16.h>
#include <cuda_fp16.h>
#include <cstdint>

#define B_   2
#define S_   2048
#define D_   1024
#define H_   16
#define DK_  64
#define BH_  (B_ * H_)
#define M_ROWS (B_ * S_)   // 4096

#define QSCALE 0.18033688011112042f   // log2(e)/sqrt(64)

// ---------------- scratch ----------------
__device__ __half g_Xhi[M_ROWS * D_];
__device__ __half g_Xlo[M_ROWS * D_];
__device__ __half g_Wth[4 * D_ * D_];     // fp16 hi of transposed weights only
__device__ __nv_bfloat16 g_Qh[BH_ * S_ * DK_];
__device__ __nv_bfloat16 g_Ql[BH_ * S_ * DK_];
__device__ __nv_bfloat16 g_Kh[BH_ * S_ * DK_];
__device__ __nv_bfloat16 g_Kl[BH_ * S_ * DK_];
__device__ __nv_bfloat16 g_Vh[BH_ * S_ * DK_];
__device__ __nv_bfloat16 g_Vl[BH_ * S_ * DK_];

// ---------------- helpers ----------------
__device__ __forceinline__ uint32_t smem_u32(const void* p) {
    uint32_t a;
    asm("{ .reg .u64 t; cvta.to.shared.u64 t, %1; cvt.u32.u64 %0, t; }" : "=r"(a) : "l"(p));
    return a;
}
__device__ __forceinline__ void ldsm4(uint32_t* r, uint32_t addr) {
    asm volatile("ldmatrix.sync.aligned.m8n8.x4.shared.b16 {%0,%1,%2,%3}, [%4];"
        : "=r"(r[0]), "=r"(r[1]), "=r"(r[2]), "=r"(r[3]) : "r"(addr));
}
__device__ __forceinline__ void ldsm4t(uint32_t* r, uint32_t addr) {
    asm volatile("ldmatrix.sync.aligned.m8n8.x4.trans.shared.b16 {%0,%1,%2,%3}, [%4];"
        : "=r"(r[0]), "=r"(r[1]), "=r"(r[2]), "=r"(r[3]) : "r"(addr));
}
// bf16 x bf16 -> fp32
__device__ __forceinline__ void mma16816(float* c, const uint32_t* a, const uint32_t* b) {
    asm volatile("mma.sync.aligned.m16n8k16.row.col.f32.bf16.bf16.f32 "
        "{%0,%1,%2,%3}, {%4,%5,%6,%7}, {%8,%9}, {%0,%1,%2,%3};"
        : "+f"(c[0]), "+f"(c[1]), "+f"(c[2]), "+f"(c[3])
        : "r"(a[0]), "r"(a[1]), "r"(a[2]), "r"(a[3]), "r"(b[0]), "r"(b[1]));
}
// fp16 x fp16 -> fp32
__device__ __forceinline__ void mma16816h(float* c, const uint32_t* a, const uint32_t* b) {
    asm volatile("mma.sync.aligned.m16n8k16.row.col.f32.f16.f16.f32 "
        "{%0,%1,%2,%3}, {%4,%5,%6,%7}, {%8,%9}, {%0,%1,%2,%3};"
        : "+f"(c[0]), "+f"(c[1]), "+f"(c[2]), "+f"(c[3])
        : "r"(a[0]), "r"(a[1]), "r"(a[2]), "r"(a[3]), "r"(b[0]), "r"(b[1]));
}
// fp16 x fp16 -> fp16 (correction pass)
__device__ __forceinline__ void mma16816hh(uint32_t* c, const uint32_t* a, const uint32_t* b) {
    asm volatile("mma.sync.aligned.m16n8k16.row.col.f16.f16.f16.f16 "
        "{%0,%1}, {%2,%3,%4,%5}, {%6,%7}, {%0,%1};"
        : "+r"(c[0]), "+r"(c[1])
        : "r"(a[0]), "r"(a[1]), "r"(a[2]), "r"(a[3]), "r"(b[0]), "r"(b[1]));
}
__device__ __forceinline__ void cpa16(uint32_t d, const void* g) {
    asm volatile("cp.async.cg.shared.global [%0], [%1], 16;" :: "r"(d), "l"(g));
}
#define CP_COMMIT() asm volatile("cp.async.commit_group;" ::: "memory")
#define CP_WAIT0()  asm volatile("cp.async.wait_group 0;" ::: "memory")

// packed bf16 hi/lo split
__device__ __forceinline__ void split2(float a, float b, uint32_t& hi, uint32_t& lo) {
    uint32_t h;
    asm("cvt.rn.bf16x2.f32 %0, %1, %2;" : "=r"(h) : "f"(b), "f"(a));
    const float fa = __uint_as_float(h << 16);
    const float fb = __uint_as_float(h & 0xffff0000u);
    const float ra = a - fa, rb = b - fb;
    uint32_t l;
    asm("cvt.rn.bf16x2.f32 %0, %1, %2;" : "=r"(l) : "f"(rb), "f"(ra));
    hi = h; lo = l;
}
// packed fp16 hi/lo split
__device__ __forceinline__ void split2h(float a, float b, uint32_t& hi, uint32_t& lo) {
    uint32_t h;
    asm("cvt.rn.f16x2.f32 %0, %1, %2;" : "=r"(h) : "f"(b), "f"(a));
    const __half2 hp = *(const __half2*)&h;
    const float fa = __half2float(__low2half(hp));
    const float fb = __half2float(__high2half(hp));
    const float ra = a - fa, rb = b - fb;
    uint32_t l;
    asm("cvt.rn.f16x2.f32 %0, %1, %2;" : "=r"(l) : "f"(rb), "f"(ra));
    hi = h; lo = l;
}

// ---------------------------------------------------------------------------
__global__ __launch_bounds__(256) void split_f16(
    const float* __restrict__ src, __half* __restrict__ hi,
    __half* __restrict__ lo, int n4)
{
    int i = blockIdx.x * blockDim.x + threadIdx.x;
    if (i >= n4) return;
    float4 v = ((const float4*)src)[i];
    uint32_t h0, l0, h1, l1;
    split2h(v.x, v.y, h0, l0);
    split2h(v.z, v.w, h1, l1);
    uint2 hu = {h0, h1}, lu = {l0, l1};
    ((uint2*)hi)[i] = hu;
    ((uint2*)lo)[i] = lu;
}

// ---------------------------------------------------------------------------
// transpose W [K,N] -> Wt hi only (fp16), 4 weights in one launch
// ---------------------------------------------------------------------------
__global__ void transpose_f16(const float* __restrict__ W0,
                              const float* __restrict__ W1,
                              const float* __restrict__ W2,
                              const float* __restrict__ W3,
                              __half* __restrict__ hi)
{
    __shared__ float t[32][33];
    const float* W = (blockIdx.z == 0) ? W0 : (blockIdx.z == 1) ? W1 :
                     (blockIdx.z == 2) ? W2 : W3;
    const int k = blockIdx.y * 32 + threadIdx.y;
    const int n = blockIdx.x * 32 + threadIdx.x;
    t[threadIdx.y][threadIdx.x] = W[(size_t)k * D_ + n];
    __syncthreads();
    const int nn = blockIdx.x * 32 + threadIdx.y + blockIdx.z * D_;
    const int kk = blockIdx.y * 32 + threadIdx.x;
    hi[(size_t)nn * D_ + kk] = __float2half_rn(t[threadIdx.x][threadIdx.y]);
}

// ---------------------------------------------------------------------------
// HMMA GEMM, 2-pass fp16 split: y = xh*wh (fp32 acc) + xl*wh (fp16 acc).
// Omits xh*wl (rel err ~2^-12). 3 slabs/stage (Ah, Al, Bh), 2-stage cp.async,
// 2 CTAs/SM.
// ---------------------------------------------------------------------------
#define GROWB 80
#define SLABB (128 * GROWB)       // 10240
#define STAGEB (3 * SLABB)        // 30720
#define GSMEM (2 * STAGEB)        // 61440

__global__ __launch_bounds__(256, 2) void gemm_tc(
    const __half* __restrict__ Ah, const __half* __restrict__ Al,
    const __half* __restrict__ Bh,
    const float* __restrict__ b0, const float* __restrict__ b1,
    const float* __restrict__ b2, float* __restrict__ Yf,
    __nv_bfloat16* __restrict__ Qh, __nv_bfloat16* __restrict__ Ql,
    __nv_bfloat16* __restrict__ Kh, __nv_bfloat16* __restrict__ Kl,
    __nv_bfloat16* __restrict__ Vh, __nv_bfloat16* __restrict__ Vl,
    int mode)
{
    extern __shared__ __align__(16) unsigned char dsm[];
    const uint32_t s0 = smem_u32(dsm);

    const int tid = threadIdx.x, wid = tid >> 5, lane = tid & 31;
    const int wm = wid >> 2, wn = wid & 3;
    const int bm = blockIdx.y * 128, bn = blockIdx.x * 128;

    const __half* gAh = Ah + (size_t)bm * 1024;
    const __half* gAl = Al + (size_t)bm * 1024;
    const __half* gBh = Bh + (size_t)bn * 1024;

    const uint32_t aRow = (uint32_t)(wm * 64 + (lane & 15));
    const uint32_t aCol = (uint32_t)(lane >> 4) * 16;
    const uint32_t bRow0 = (uint32_t)(wn * 32 + ((lane >> 4) & 1) * 8 + (lane & 7));
    const uint32_t bKoff = (uint32_t)((lane >> 3) & 1) * 16;

    float acc[16][4];
    uint32_t facc[16][2];
#pragma unroll
    for (int i = 0; i < 16; i++) {
#pragma unroll
        for (int j = 0; j < 4; j++) acc[i][j] = 0.f;
        facc[i][0] = 0u; facc[i][1] = 0u;
    }

    // 6 chunks of 16B per thread: p=0,1 -> Ah; p=2,3 -> Al; p=4,5 -> Bh
    auto issue = [&](int ks) {
        const uint32_t st = s0 + (uint32_t)(ks & 1) * STAGEB;
#pragma unroll
        for (int p = 0; p < 6; p++) {
            const int id = p * 256 + tid;
            const int slab = id >> 9;            // const per p (tid < 256)
            const int within = id & 511;
            const int row = within >> 2, ch = within & 3;
            const __half* base = (slab == 0) ? gAh : (slab == 1) ? gAl : gBh;
            cpa16(st + (uint32_t)slab * SLABB + (uint32_t)row * GROWB + (uint32_t)ch * 16,
                  base + ks * 32 + (size_t)row * 1024 + ch * 8);
        }
        CP_COMMIT();
    };

    issue(0);

    for (int ks = 0; ks < 32; ks++) {
        CP_WAIT0();
        __syncthreads();
        if (ks + 1 < 32) issue(ks + 1);

        const uint32_t sb  = s0 + (uint32_t)(ks & 1) * STAGEB;
        const uint32_t SAh = sb, SAl = sb + SLABB, SBh = sb + 2 * SLABB;

#pragma unroll
        for (int h = 0; h < 2; h++) {
            uint32_t fA[4][4], fB[4][2];
            const uint32_t hoff = (uint32_t)h * 32;
#pragma unroll
            for (int mt = 0; mt < 4; mt++)
                ldsm4(fA[mt], SAh + (aRow + (uint32_t)(mt * 16)) * GROWB + hoff + aCol);
#pragma unroll
            for (int g = 0; g < 2; g++) {
                uint32_t r[4];
                ldsm4(r, SBh + (bRow0 + (uint32_t)(g * 16)) * GROWB + hoff + bKoff);
                fB[g * 2][0] = r[0]; fB[g * 2][1] = r[1];
                fB[g * 2 + 1][0] = r[2]; fB[g * 2 + 1][1] = r[3];
            }
            // pass 1: Ah x Bh (fp32 acc)
#pragma unroll
            for (int mt = 0; mt < 4; mt++)
#pragma unroll
                for (int nt = 0; nt < 4; nt++)
                    mma16816h(acc[mt * 4 + nt], fA[mt], fB[nt]);
            // pass 2: Al x Bh (fp16 acc)
#pragma unroll
            for (int mt = 0; mt < 4; mt++)
                ldsm4(fA[mt], SAl + (aRow + (uint32_t)(mt * 16)) * GROWB + hoff + aCol);
#pragma unroll
            for (int mt = 0; mt < 4; mt++)
#pragma unroll
                for (int nt = 0; nt < 4; nt++)
                    mma16816hh(facc[mt * 4 + nt], fA[mt], fB[nt]);
        }
    }

    // ---- epilogue: main + fp16 correction + bias ----
    const int qr = lane >> 2, qc = (lane & 3) * 2;
    const int proj = bn >> 10;
    const float* bias = (proj == 0) ? b0 : (proj == 1) ? b1 : b2;
    const float scale = (mode == 1 && proj == 0) ? QSCALE : 1.0f;
    __nv_bfloat16* Yh = (proj == 0) ? Qh : (proj == 1) ? Kh : Vh;
    __nv_bfloat16* Yl = (proj == 0) ? Ql : (proj == 1) ? Kl : Vl;
    const int bnl = bn & 1023;

#pragma unroll
    for (int mt = 0; mt < 4; mt++) {
#pragma unroll
        for (int nt = 0; nt < 4; nt++) {
            const int i = mt * 4 + nt;
            const __half2 c01 = *(const __half2*)&facc[i][0];
            const __half2 c23 = *(const __half2*)&facc[i][1];
            const float v0f = acc[i][0] + __half2float(__low2half(c01));
            const float v1f = acc[i][1] + __half2float(__high2half(c01));
            const float v2f = acc[i][2] + __half2float(__low2half(c23));
            const float v3f = acc[i][3] + __half2float(__high2half(c23));
            const int r0 = bm + wm * 64 + mt * 16 + qr;
            const int cn = bnl + wn * 32 + nt * 8 + qc;
            const float bv0 = bias[cn], bv1 = bias[cn + 1];
            if (mode == 0) {
                float2 v0 = {v0f + bv0, v1f + bv1};
                float2 v1 = {v2f + bv0, v3f + bv1};
                *(float2*)(Yf + (size_t)r0 * 1024 + cn) = v0;
                *(float2*)(Yf + (size_t)(r0 + 8) * 1024 + cn) = v1;
            } else {
                const float w0 = (v0f + bv0) * scale, w1 = (v1f + bv1) * scale;
                const float w2 = (v2f + bv0) * scale, w3 = (v3f + bv1) * scale;
                const int h  = cn >> 6, dk = cn & 63;
                const int b0i = r0 >> 11, s0i = r0 & 2047;
                const int b1i = (r0 + 8) >> 11, s1i = (r0 + 8) & 2047;
                const size_t o0 = (((size_t)(b0i * H_ + h)) * S_ + s0i) * DK_ + dk;
                const size_t o1 = (((size_t)(b1i * H_ + h)) * S_ + s1i) * DK_ + dk;
                uint32_t h0, l0, h1, l1;
                split2(w0, w1, h0, l0);
                split2(w2, w3, h1, l1);
                *(uint32_t*)(Yh + o0) = h0; *(uint32_t*)(Yl + o0) = l0;
                *(uint32_t*)(Yh + o1) = h1; *(uint32_t*)(Yl + o1) = l1;
            }
        }
    }
}

// ---------------------------------------------------------------------------
// Flash attention (causal): R10 config verbatim (best measured: 164.5us).
// 128 thr / 64 q-rows, 2 CTAs/SM, bf16 3-pass HMMA, skip-rescale,
// fp16 hi/lo ctx output.
// ---------------------------------------------------------------------------
#define ASMEM 81920

__global__ __launch_bounds__(128, 2) void flash_attn_tc(
    const __nv_bfloat16* __restrict__ Qh, const __nv_bfloat16* __restrict__ Ql,
    const __nv_bfloat16* __restrict__ Kh, const __nv_bfloat16* __restrict__ Kl,
    const __nv_bfloat16* __restrict__ Vh, const __nv_bfloat16* __restrict__ Vl,
    __half* __restrict__ Ohi, __half* __restrict__ Olo)
{
    extern __shared__ __align__(16) unsigned char sm[];
    const uint32_t s0 = smem_u32(sm);

    const int tid = threadIdx.x, wid = tid >> 5, lane = tid & 31;
    const int qt = 31 - blockIdx.x;
    const int bh = blockIdx.y;
    const int qbase = qt * 64;
    const int njt = qt + 1;
    const int rb = wid * 16;

    {
        const int arr = tid >> 6;
        const int t2 = tid & 63;
        const __nv_bfloat16* base = (arr ? Ql : Qh) + ((size_t)bh * S_ + qbase) * DK_;
        const uint32_t db = (uint32_t)arr * 8192;
#pragma unroll
        for (int p = 0; p < 8; p++) {
            const int idx = p * 64 + t2;
            const int row = idx >> 3, ch = idx & 7;
            *(uint4*)(sm + db + (uint32_t)row * 128 + (uint32_t)((ch ^ (row & 7)) << 4)) =
                *(const uint4*)(base + (size_t)row * 64 + ch * 8);
        }
    }
    __syncthreads();

    uint32_t qfh[4][4], qfl[4][4];
    {
        const int row = rb + (lane & 15);
        const int r7 = row & 7;
#pragma unroll
        for (int kk = 0; kk < 4; kk++) {
            const uint32_t a = s0 + (uint32_t)row * 128 +
                (uint32_t)(((2 * kk + (lane >> 4)) ^ r7) << 4);
            ldsm4(qfh[kk], a);
            ldsm4(qfl[kk], a + 8192);
        }
    }
    __syncthreads();

    const int a4  = tid >> 5;
    const int t5  = tid & 31;
    const __nv_bfloat16* kvsrc =
        (a4 == 0) ? Kh : (a4 == 1) ? Kl : (a4 == 2) ? Vh : Vl;
    kvsrc += (size_t)bh * S_ * DK_;
    const uint32_t kvdst = s0 + 16384 + (uint32_t)a4 * 8192;

    {
        const __nv_bfloat16* g = kvsrc;
#pragma unroll
        for (int p = 0; p < 16; p++) {
            const int idx = p * 32 + t5;
            const int row = idx >> 3, ch = idx & 7;
            cpa16(kvdst + (uint32_t)row * 128 + (uint32_t)((ch ^ (row & 7)) << 4),
                  g + (size_t)row * 64 + ch * 8);
        }
    }
    CP_COMMIT();

    float m_i[2] = {-1e30f, -1e30f};
    float l_i[2] = {0.f, 0.f};
    float oac[8][4];
#pragma unroll
    for (int t = 0; t < 8; t++)
#pragma unroll
        for (int e = 0; e < 4; e++) oac[t][e] = 0.f;

    for (int jt = 0; jt < njt; jt++) {
        CP_WAIT0();
        __syncthreads();
        const uint32_t bb = s0 + 16384 + (uint32_t)(jt & 1) * 32768;

        if (jt + 1 < njt) {
            const __nv_bfloat16* g = kvsrc + (size_t)(jt + 1) * 64 * 64;
            const uint32_t db = kvdst + (uint32_t)((jt + 1) & 1) * 32768;
#pragma unroll
            for (int p = 0; p < 16; p++) {
                const int idx = p * 32 + t5;
                const int row = idx >> 3, ch = idx & 7;
                cpa16(db + (uint32_t)row * 128 + (uint32_t)((ch ^ (row & 7)) << 4),
                      g + (size_t)row * 64 + ch * 8);
            }
            CP_COMMIT();
        }

        float sc[8][4];
#pragma unroll
        for (int t = 0; t < 8; t++)
#pragma unroll
            for (int e = 0; e < 4; e++) sc[t][e] = 0.f;

#pragma unroll
        for (int kk = 0; kk < 4; kk++) {
#pragma unroll
            for (int j = 0; j < 4; j++) {
                const int krow = 16 * j + (lane & 7) + ((lane & 16) >> 1);
                const uint32_t ka = bb + (uint32_t)krow * 128 +
                    (uint32_t)(((2 * kk + ((lane >> 3) & 1)) ^ (krow & 7)) << 4);
                uint32_t bhf[4], blf[4];
                ldsm4(bhf, ka);
                ldsm4(blf, ka + 8192);
                mma16816(sc[2 * j],     qfh[kk], bhf + 0);
                mma16816(sc[2 * j + 1], qfh[kk], bhf + 2);
                mma16816(sc[2 * j],     qfh[kk], blf + 0);
                mma16816(sc[2 * j + 1], qfh[kk], blf + 2);
                mma16816(sc[2 * j],     qfl[kk], bhf + 0);
                mma16816(sc[2 * j + 1], qfl[kk], bhf + 2);
            }
        }

        if (jt == njt - 1) {
#pragma unroll
            for (int t = 0; t < 8; t++)
#pragma unroll
                for (int e = 0; e < 4; e++) {
                    const int kg = t * 8 + 2 * (lane & 3) + (e & 1);
                    const int qg = rb + (lane >> 2) + (e >> 1) * 8;
                    if (kg > qg) sc[t][e] = -1e9f;
                }
        }

#pragma unroll
        for (int h = 0; h < 2; h++) {
            float mr = -1e30f;
#pragma unroll
            for (int t = 0; t < 8; t++)
                mr = fmaxf(mr, fmaxf(sc[t][2 * h], sc[t][2 * h + 1]));
            mr = fmaxf(mr, __shfl_xor_sync(0xffffffffu, mr, 1));
            mr = fmaxf(mr, __shfl_xor_sync(0xffffffffu, mr, 2));
            const float mn = fmaxf(m_i[h], mr);
            if (__any_sync(0xffffffffu, mn != m_i[h])) {
                const float alpha = exp2f(m_i[h] - mn);
                m_i[h] = mn;
                l_i[h] *= alpha;
#pragma unroll
                for (int t = 0; t < 8; t++) {
                    oac[t][2 * h]     *= alpha;
                    oac[t][2 * h + 1] *= alpha;
                }
            }
            float rs = 0.f;
#pragma unroll
            for (int t = 0; t < 8; t++) {
                sc[t][2 * h]     = exp2f(sc[t][2 * h] - mn);
                sc[t][2 * h + 1] = exp2f(sc[t][2 * h + 1] - mn);
                rs += sc[t][2 * h] + sc[t][2 * h + 1];
            }
            rs += __shfl_xor_sync(0xffffffffu, rs, 1);
            rs += __shfl_xor_sync(0xffffffffu, rs, 2);
            l_i[h] += rs;
        }

#pragma unroll
        for (int kk = 0; kk < 4; kk++) {
            uint32_t pah[4], pal[4];
            split2(sc[2 * kk][0],     sc[2 * kk][1],     pah[0], pal[0]);
            split2(sc[2 * kk][2],     sc[2 * kk][3],     pah[1], pal[1]);
            split2(sc[2 * kk + 1][0], sc[2 * kk + 1][1], pah[2], pal[2]);
            split2(sc[2 * kk + 1][2], sc[2 * kk + 1][3], pah[3], pal[3]);

            const int vrow = 16 * kk + (lane & 15);
            const int vr7 = vrow & 7;
#pragma unroll
            for (int j = 0; j < 4; j++) {
                const uint32_t va = bb + 16384 + (uint32_t)vrow * 128 +
                    (uint32_t)(((2 * j + (lane >> 4)) ^ vr7) << 4);
                uint32_t vhf[4], vlf[4];
                ldsm4t(vhf, va);
                ldsm4t(vlf, va + 8192);
                mma16816(oac[2 * j],     pah, vhf + 0);
                mma16816(oac[2 * j + 1], pah, vhf + 2);
                mma16816(oac[2 * j],     pah, vlf + 0);
                mma16816(oac[2 * j + 1], pah, vlf + 2);
                mma16816(oac[2 * j],     pal, vhf + 0);
                mma16816(oac[2 * j + 1], pal, vhf + 2);
            }
        }
    }

    const int bb_ = bh >> 4, hh = bh & 15;
#pragma unroll
    for (int h = 0; h < 2; h++) {
        const float invl = 1.f / l_i[h];
        const int rg = qbase + rb + (lane >> 2) + 8 * h;
        const size_t mrow = (size_t)(bb_ * 2048 + rg) * 1024;
#pragma unroll
        for (int t = 0; t < 8; t++) {
            const float v0 = oac[t][2 * h] * invl;
            const float v1 = oac[t][2 * h + 1] * invl;
            const int col = hh * 64 + t * 8 + 2 * (lane & 3);
            uint32_t hi, lo;
            split2h(v0, v1, hi, lo);
            *(uint32_t*)(Ohi + mrow + col) = hi;
            *(uint32_t*)(Olo + mrow + col) = lo;
        }
    }
}

// ---------------------------------------------------------------------------
extern "C" void kernel_launch(void* const* d_in, const int* in_sizes, int n_in,
                              void* d_out, int out_size)
{
    const float* x  = (const float*)d_in[0];
    const float* Wq = (const float*)d_in[2];
    const float* bq = (const float*)d_in[3];
    const float* Wk = (const float*)d_in[4];
    const float* bk = (const float*)d_in[5];
    const float* Wv = (const float*)d_in[6];
    const float* bv = (const float*)d_in[7];
    const float* Wo = (const float*)d_in[8];
    const float* bo = (const float*)d_in[9];

    __half *xh, *xl, *wth;
    __nv_bfloat16 *qh, *ql, *kh, *kl, *vh, *vl;
    cudaGetSymbolAddress((void**)&xh, g_Xhi);
    cudaGetSymbolAddress((void**)&xl, g_Xlo);
    cudaGetSymbolAddress((void**)&wth, g_Wth);
    cudaGetSymbolAddress((void**)&qh, g_Qh);
    cudaGetSymbolAddress((void**)&ql, g_Ql);
    cudaGetSymbolAddress((void**)&kh, g_Kh);
    cudaGetSymbolAddress((void**)&kl, g_Kl);
    cudaGetSymbolAddress((void**)&vh, g_Vh);
    cudaGetSymbolAddress((void**)&vl, g_Vl);

    const int n4 = M_ROWS * D_ / 4;
    const dim3 tb(32, 32);

    cudaFuncSetAttribute(gemm_tc, cudaFuncAttributeMaxDynamicSharedMemorySize, GSMEM);
    cudaFuncSetAttribute(flash_attn_tc, cudaFuncAttributeMaxDynamicSharedMemorySize, ASMEM);

    split_f16<<<(n4 + 255) / 256, 256>>>(x, xh, xl, n4);
    transpose_f16<<<dim3(32, 32, 4), tb>>>(Wq, Wk, Wv, Wo, wth);

    gemm_tc<<<dim3(24, 32), 256, GSMEM>>>(xh, xl, wth, bq, bk, bv,
                                          nullptr, qh, ql, kh, kl, vh, vl, 1);

    flash_attn_tc<<<dim3(32, BH_), 128, ASMEM>>>(qh, ql, kh, kl, vh, vl, xh, xl);

    gemm_tc<<<dim3(8, 32), 256, GSMEM>>>(xh, xl, wth + 3 * D_ * D_,
                                         bo, bo, bo, (float*)d_out,
                                         nullptr, nullptr, nullptr, nullptr,
                                         nullptr, nullptr, 0);
}

// round 14
// speedup vs baseline: 1.2922x; 1.1274x over previous
#include <cuda_runtime.h>
#include <cuda_bf16.h>
#include <cuda_fp16.h>
#include <cstdint>

#define B_   2
#define S_   2048
#define D_   1024
#define H_   16
#define DK_  64
#define BH_  (B_ * H_)
#define M_ROWS (B_ * S_)   // 4096

#define QSCALE 0.18033688011112042f   // log2(e)/sqrt(64)

// ---------------- scratch ----------------
__device__ __half g_Xhi[M_ROWS * D_];
__device__ __half g_Xlo[M_ROWS * D_];
__device__ __half g_Wth[4 * D_ * D_];
__device__ __half g_Qh[BH_ * S_ * DK_];
__device__ __half g_Ql[BH_ * S_ * DK_];
__device__ __half g_Kh[BH_ * S_ * DK_];
__device__ __half g_Vh[BH_ * S_ * DK_];

// ---------------- helpers ----------------
__device__ __forceinline__ uint32_t smem_u32(const void* p) {
    uint32_t a;
    asm("{ .reg .u64 t; cvta.to.shared.u64 t, %1; cvt.u32.u64 %0, t; }" : "=r"(a) : "l"(p));
    return a;
}
__device__ __forceinline__ void ldsm4(uint32_t* r, uint32_t addr) {
    asm volatile("ldmatrix.sync.aligned.m8n8.x4.shared.b16 {%0,%1,%2,%3}, [%4];"
        : "=r"(r[0]), "=r"(r[1]), "=r"(r[2]), "=r"(r[3]) : "r"(addr));
}
__device__ __forceinline__ void ldsm4t(uint32_t* r, uint32_t addr) {
    asm volatile("ldmatrix.sync.aligned.m8n8.x4.trans.shared.b16 {%0,%1,%2,%3}, [%4];"
        : "=r"(r[0]), "=r"(r[1]), "=r"(r[2]), "=r"(r[3]) : "r"(addr));
}
// fp16 x fp16 -> fp32
__device__ __forceinline__ void mma16816h(float* c, const uint32_t* a, const uint32_t* b) {
    asm volatile("mma.sync.aligned.m16n8k16.row.col.f32.f16.f16.f32 "
        "{%0,%1,%2,%3}, {%4,%5,%6,%7}, {%8,%9}, {%0,%1,%2,%3};"
        : "+f"(c[0]), "+f"(c[1]), "+f"(c[2]), "+f"(c[3])
        : "r"(a[0]), "r"(a[1]), "r"(a[2]), "r"(a[3]), "r"(b[0]), "r"(b[1]));
}
// fp16 x fp16 -> fp16 (GEMM correction pass)
__device__ __forceinline__ void mma16816hh(uint32_t* c, const uint32_t* a, const uint32_t* b) {
    asm volatile("mma.sync.aligned.m16n8k16.row.col.f16.f16.f16.f16 "
        "{%0,%1}, {%2,%3,%4,%5}, {%6,%7}, {%0,%1};"
        : "+r"(c[0]), "+r"(c[1])
        : "r"(a[0]), "r"(a[1]), "r"(a[2]), "r"(a[3]), "r"(b[0]), "r"(b[1]));
}
__device__ __forceinline__ void cpa16(uint32_t d, const void* g) {
    asm volatile("cp.async.cg.shared.global [%0], [%1], 16;" :: "r"(d), "l"(g));
}
#define CP_COMMIT() asm volatile("cp.async.commit_group;" ::: "memory")
#define CP_WAIT0()  asm volatile("cp.async.wait_group 0;" ::: "memory")

// packed fp16 pair (no split)
__device__ __forceinline__ uint32_t f16pack(float a, float b) {
    uint32_t h;
    asm("cvt.rn.f16x2.f32 %0, %1, %2;" : "=r"(h) : "f"(b), "f"(a));
    return h;
}
// packed fp16 hi/lo split
__device__ __forceinline__ void split2h(float a, float b, uint32_t& hi, uint32_t& lo) {
    uint32_t h;
    asm("cvt.rn.f16x2.f32 %0, %1, %2;" : "=r"(h) : "f"(b), "f"(a));
    const __half2 hp = *(const __half2*)&h;
    const float fa = __half2float(__low2half(hp));
    const float fb = __half2float(__high2half(hp));
    const float ra = a - fa, rb = b - fb;
    uint32_t l;
    asm("cvt.rn.f16x2.f32 %0, %1, %2;" : "=r"(l) : "f"(rb), "f"(ra));
    hi = h; lo = l;
}

// ---------------------------------------------------------------------------
__global__ __launch_bounds__(256) void split_f16(
    const float* __restrict__ src, __half* __restrict__ hi,
    __half* __restrict__ lo, int n4)
{
    int i = blockIdx.x * blockDim.x + threadIdx.x;
    if (i >= n4) return;
    float4 v = ((const float4*)src)[i];
    uint32_t h0, l0, h1, l1;
    split2h(v.x, v.y, h0, l0);
    split2h(v.z, v.w, h1, l1);
    uint2 hu = {h0, h1}, lu = {l0, l1};
    ((uint2*)hi)[i] = hu;
    ((uint2*)lo)[i] = lu;
}

// ---------------------------------------------------------------------------
__global__ void transpose_f16(const float* __restrict__ W0,
                              const float* __restrict__ W1,
                              const float* __restrict__ W2,
                              const float* __restrict__ W3,
                              __half* __restrict__ hi)
{
    __shared__ float t[32][33];
    const float* W = (blockIdx.z == 0) ? W0 : (blockIdx.z == 1) ? W1 :
                     (blockIdx.z == 2) ? W2 : W3;
    const int k = blockIdx.y * 32 + threadIdx.y;
    const int n = blockIdx.x * 32 + threadIdx.x;
    t[threadIdx.y][threadIdx.x] = W[(size_t)k * D_ + n];
    __syncthreads();
    const int nn = blockIdx.x * 32 + threadIdx.y + blockIdx.z * D_;
    const int kk = blockIdx.y * 32 + threadIdx.x;
    hi[(size_t)nn * D_ + kk] = __float2half_rn(t[threadIdx.x][threadIdx.y]);
}

// ---------------------------------------------------------------------------
// HMMA GEMM (R13 structure): y = xh*wh (fp32 acc) + xl*wh (fp16 acc).
// mode 1 epilogue: Q -> fp16 hi/lo pair (scaled); K,V -> single fp16 array.
// ---------------------------------------------------------------------------
#define GROWB 80
#define SLABB (128 * GROWB)       // 10240
#define STAGEB (3 * SLABB)        // 30720
#define GSMEM (2 * STAGEB)        // 61440

__global__ __launch_bounds__(256, 2) void gemm_tc(
    const __half* __restrict__ Ah, const __half* __restrict__ Al,
    const __half* __restrict__ Bh,
    const float* __restrict__ b0, const float* __restrict__ b1,
    const float* __restrict__ b2, float* __restrict__ Yf,
    __half* __restrict__ Qh, __half* __restrict__ Ql,
    __half* __restrict__ Kh, __half* __restrict__ Vh,
    int mode)
{
    extern __shared__ __align__(16) unsigned char dsm[];
    const uint32_t s0 = smem_u32(dsm);

    const int tid = threadIdx.x, wid = tid >> 5, lane = tid & 31;
    const int wm = wid >> 2, wn = wid & 3;
    const int bm = blockIdx.y * 128, bn = blockIdx.x * 128;

    const __half* gAh = Ah + (size_t)bm * 1024;
    const __half* gAl = Al + (size_t)bm * 1024;
    const __half* gBh = Bh + (size_t)bn * 1024;

    const uint32_t aRow = (uint32_t)(wm * 64 + (lane & 15));
    const uint32_t aCol = (uint32_t)(lane >> 4) * 16;
    const uint32_t bRow0 = (uint32_t)(wn * 32 + ((lane >> 4) & 1) * 8 + (lane & 7));
    const uint32_t bKoff = (uint32_t)((lane >> 3) & 1) * 16;

    float acc[16][4];
    uint32_t facc[16][2];
#pragma unroll
    for (int i = 0; i < 16; i++) {
#pragma unroll
        for (int j = 0; j < 4; j++) acc[i][j] = 0.f;
        facc[i][0] = 0u; facc[i][1] = 0u;
    }

    auto issue = [&](int ks) {
        const uint32_t st = s0 + (uint32_t)(ks & 1) * STAGEB;
#pragma unroll
        for (int p = 0; p < 6; p++) {
            const int id = p * 256 + tid;
            const int slab = id >> 9;
            const int within = id & 511;
            const int row = within >> 2, ch = within & 3;
            const __half* base = (slab == 0) ? gAh : (slab == 1) ? gAl : gBh;
            cpa16(st + (uint32_t)slab * SLABB + (uint32_t)row * GROWB + (uint32_t)ch * 16,
                  base + ks * 32 + (size_t)row * 1024 + ch * 8);
        }
        CP_COMMIT();
    };

    issue(0);

    for (int ks = 0; ks < 32; ks++) {
        CP_WAIT0();
        __syncthreads();
        if (ks + 1 < 32) issue(ks + 1);

        const uint32_t sb  = s0 + (uint32_t)(ks & 1) * STAGEB;
        const uint32_t SAh = sb, SAl = sb + SLABB, SBh = sb + 2 * SLABB;

#pragma unroll
        for (int h = 0; h < 2; h++) {
            uint32_t fA[4][4], fB[4][2];
            const uint32_t hoff = (uint32_t)h * 32;
#pragma unroll
            for (int mt = 0; mt < 4; mt++)
                ldsm4(fA[mt], SAh + (aRow + (uint32_t)(mt * 16)) * GROWB + hoff + aCol);
#pragma unroll
            for (int g = 0; g < 2; g++) {
                uint32_t r[4];
                ldsm4(r, SBh + (bRow0 + (uint32_t)(g * 16)) * GROWB + hoff + bKoff);
                fB[g * 2][0] = r[0]; fB[g * 2][1] = r[1];
                fB[g * 2 + 1][0] = r[2]; fB[g * 2 + 1][1] = r[3];
            }
#pragma unroll
            for (int mt = 0; mt < 4; mt++)
#pragma unroll
                for (int nt = 0; nt < 4; nt++)
                    mma16816h(acc[mt * 4 + nt], fA[mt], fB[nt]);
#pragma unroll
            for (int mt = 0; mt < 4; mt++)
                ldsm4(fA[mt], SAl + (aRow + (uint32_t)(mt * 16)) * GROWB + hoff + aCol);
#pragma unroll
            for (int mt = 0; mt < 4; mt++)
#pragma unroll
                for (int nt = 0; nt < 4; nt++)
                    mma16816hh(facc[mt * 4 + nt], fA[mt], fB[nt]);
        }
    }

    // ---- epilogue ----
    const int qr = lane >> 2, qc = (lane & 3) * 2;
    const int proj = bn >> 10;
    const float* bias = (proj == 0) ? b0 : (proj == 1) ? b1 : b2;
    const float scale = (mode == 1 && proj == 0) ? QSCALE : 1.0f;
    const int bnl = bn & 1023;

#pragma unroll
    for (int mt = 0; mt < 4; mt++) {
#pragma unroll
        for (int nt = 0; nt < 4; nt++) {
            const int i = mt * 4 + nt;
            const __half2 c01 = *(const __half2*)&facc[i][0];
            const __half2 c23 = *(const __half2*)&facc[i][1];
            const float v0f = acc[i][0] + __half2float(__low2half(c01));
            const float v1f = acc[i][1] + __half2float(__high2half(c01));
            const float v2f = acc[i][2] + __half2float(__low2half(c23));
            const float v3f = acc[i][3] + __half2float(__high2half(c23));
            const int r0 = bm + wm * 64 + mt * 16 + qr;
            const int cn = bnl + wn * 32 + nt * 8 + qc;
            const float bv0 = bias[cn], bv1 = bias[cn + 1];
            if (mode == 0) {
                float2 v0 = {v0f + bv0, v1f + bv1};
                float2 v1 = {v2f + bv0, v3f + bv1};
                *(float2*)(Yf + (size_t)r0 * 1024 + cn) = v0;
                *(float2*)(Yf + (size_t)(r0 + 8) * 1024 + cn) = v1;
            } else {
                const float w0 = (v0f + bv0) * scale, w1 = (v1f + bv1) * scale;
                const float w2 = (v2f + bv0) * scale, w3 = (v3f + bv1) * scale;
                const int h  = cn >> 6, dk = cn & 63;
                const int b0i = r0 >> 11, s0i = r0 & 2047;
                const int b1i = (r0 + 8) >> 11, s1i = (r0 + 8) & 2047;
                const size_t o0 = (((size_t)(b0i * H_ + h)) * S_ + s0i) * DK_ + dk;
                const size_t o1 = (((size_t)(b1i * H_ + h)) * S_ + s1i) * DK_ + dk;
                if (proj == 0) {
                    uint32_t h0, l0, h1, l1;
                    split2h(w0, w1, h0, l0);
                    split2h(w2, w3, h1, l1);
                    *(uint32_t*)(Qh + o0) = h0; *(uint32_t*)(Ql + o0) = l0;
                    *(uint32_t*)(Qh + o1) = h1; *(uint32_t*)(Ql + o1) = l1;
                } else {
                    __half* Y = (proj == 1) ? Kh : Vh;
                    *(uint32_t*)(Y + o0) = f16pack(w0, w1);
                    *(uint32_t*)(Y + o1) = f16pack(w2, w3);
                }
            }
        }
    }
}

// ---------------------------------------------------------------------------
// Flash attention (causal), fp16 exact-operand 2-pass:
//   scores = (qh+ql) . kh      (2 MMAs per frag pair; Kl never exists)
//   oac   += (ph+pl) . vh      (2 MMAs per frag pair; Vl never exists)
// 128 thr / 64 q-rows, 2 CTAs/SM.
// smem: Qh@0, Ql@8192 (16K); stage st at 16384+st*16384: Kh+0, Vh+8192. 48K.
// ---------------------------------------------------------------------------
#define ASMEM 49152

__global__ __launch_bounds__(128, 2) void flash_attn_tc(
    const __half* __restrict__ Qh, const __half* __restrict__ Ql,
    const __half* __restrict__ Kh, const __half* __restrict__ Vh,
    __half* __restrict__ Ohi, __half* __restrict__ Olo)
{
    extern __shared__ __align__(16) unsigned char sm[];
    const uint32_t s0 = smem_u32(sm);

    const int tid = threadIdx.x, wid = tid >> 5, lane = tid & 31;
    const int qt = 31 - blockIdx.x;
    const int bh = blockIdx.y;
    const int qbase = qt * 64;
    const int njt = qt + 1;
    const int rb = wid * 16;

    // ---- stage Q (hi@0, lo@8192) ----
    {
        const int arr = tid >> 6;
        const int t2 = tid & 63;
        const __half* base = (arr ? Ql : Qh) + ((size_t)bh * S_ + qbase) * DK_;
        const uint32_t db = (uint32_t)arr * 8192;
#pragma unroll
        for (int p = 0; p < 8; p++) {
            const int idx = p * 64 + t2;
            const int row = idx >> 3, ch = idx & 7;
            *(uint4*)(sm + db + (uint32_t)row * 128 + (uint32_t)((ch ^ (row & 7)) << 4)) =
                *(const uint4*)(base + (size_t)row * 64 + ch * 8);
        }
    }
    __syncthreads();

    uint32_t qfh[4][4], qfl[4][4];
    {
        const int row = rb + (lane & 15);
        const int r7 = row & 7;
#pragma unroll
        for (int kk = 0; kk < 4; kk++) {
            const uint32_t a = s0 + (uint32_t)row * 128 +
                (uint32_t)(((2 * kk + (lane >> 4)) ^ r7) << 4);
            ldsm4(qfh[kk], a);
            ldsm4(qfl[kk], a + 8192);
        }
    }
    __syncthreads();

    // ---- KV copy geometry: 2 arrays x 64 threads, 8x16B each ----
    const int a2 = tid >> 6;                 // 0:Kh 1:Vh
    const int t6 = tid & 63;
    const __half* kvsrc = (a2 == 0) ? Kh : Vh;
    kvsrc += (size_t)bh * S_ * DK_;
    const uint32_t kvdst = s0 + 16384 + (uint32_t)a2 * 8192;

    {
        const __half* g = kvsrc;
#pragma unroll
        for (int p = 0; p < 8; p++) {
            const int idx = p * 64 + t6;
            const int row = idx >> 3, ch = idx & 7;
            cpa16(kvdst + (uint32_t)row * 128 + (uint32_t)((ch ^ (row & 7)) << 4),
                  g + (size_t)row * 64 + ch * 8);
        }
    }
    CP_COMMIT();

    float m_i[2] = {-1e30f, -1e30f};
    float l_i[2] = {0.f, 0.f};
    float oac[8][4];
#pragma unroll
    for (int t = 0; t < 8; t++)
#pragma unroll
        for (int e = 0; e < 4; e++) oac[t][e] = 0.f;

    for (int jt = 0; jt < njt; jt++) {
        CP_WAIT0();
        __syncthreads();
        const uint32_t bb = s0 + 16384 + (uint32_t)(jt & 1) * 16384;

        if (jt + 1 < njt) {
            const __half* g = kvsrc + (size_t)(jt + 1) * 64 * 64;
            const uint32_t db = kvdst + (uint32_t)((jt + 1) & 1) * 16384;
#pragma unroll
            for (int p = 0; p < 8; p++) {
                const int idx = p * 64 + t6;
                const int row = idx >> 3, ch = idx & 7;
                cpa16(db + (uint32_t)row * 128 + (uint32_t)((ch ^ (row & 7)) << 4),
                      g + (size_t)row * 64 + ch * 8);
            }
            CP_COMMIT();
        }

        // ---- scores: (qh + ql) . kh ----
        float sc[8][4];
#pragma unroll
        for (int t = 0; t < 8; t++)
#pragma unroll
            for (int e = 0; e < 4; e++) sc[t][e] = 0.f;

#pragma unroll
        for (int kk = 0; kk < 4; kk++) {
#pragma unroll
            for (int j = 0; j < 4; j++) {
                const int krow = 16 * j + (lane & 7) + ((lane & 16) >> 1);
                const uint32_t ka = bb + (uint32_t)krow * 128 +
                    (uint32_t)(((2 * kk + ((lane >> 3) & 1)) ^ (krow & 7)) << 4);
                uint32_t khf[4];
                ldsm4(khf, ka);
                mma16816h(sc[2 * j],     qfh[kk], khf + 0);
                mma16816h(sc[2 * j + 1], qfh[kk], khf + 2);
                mma16816h(sc[2 * j],     qfl[kk], khf + 0);
                mma16816h(sc[2 * j + 1], qfl[kk], khf + 2);
            }
        }

        if (jt == njt - 1) {
#pragma unroll
            for (int t = 0; t < 8; t++)
#pragma unroll
                for (int e = 0; e < 4; e++) {
                    const int kg = t * 8 + 2 * (lane & 3) + (e & 1);
                    const int qg = rb + (lane >> 2) + (e >> 1) * 8;
                    if (kg > qg) sc[t][e] = -1e9f;
                }
        }

        // ---- online softmax ----
#pragma unroll
        for (int h = 0; h < 2; h++) {
            float mr = -1e30f;
#pragma unroll
            for (int t = 0; t < 8; t++)
                mr = fmaxf(mr, fmaxf(sc[t][2 * h], sc[t][2 * h + 1]));
            mr = fmaxf(mr, __shfl_xor_sync(0xffffffffu, mr, 1));
            mr = fmaxf(mr, __shfl_xor_sync(0xffffffffu, mr, 2));
            const float mn = fmaxf(m_i[h], mr);
            if (__any_sync(0xffffffffu, mn != m_i[h])) {
                const float alpha = exp2f(m_i[h] - mn);
                m_i[h] = mn;
                l_i[h] *= alpha;
#pragma unroll
                for (int t = 0; t < 8; t++) {
                    oac[t][2 * h]     *= alpha;
                    oac[t][2 * h + 1] *= alpha;
                }
            }
            float rs = 0.f;
#pragma unroll
            for (int t = 0; t < 8; t++) {
                sc[t][2 * h]     = exp2f(sc[t][2 * h] - mn);
                sc[t][2 * h + 1] = exp2f(sc[t][2 * h + 1] - mn);
                rs += sc[t][2 * h] + sc[t][2 * h + 1];
            }
            rs += __shfl_xor_sync(0xffffffffu, rs, 1);
            rs += __shfl_xor_sync(0xffffffffu, rs, 2);
            l_i[h] += rs;
        }

        // ---- PV: (ph + pl) . vh ----
#pragma unroll
        for (int kk = 0; kk < 4; kk++) {
            uint32_t pah[4], pal[4];
            split2h(sc[2 * kk][0],     sc[2 * kk][1],     pah[0], pal[0]);
            split2h(sc[2 * kk][2],     sc[2 * kk][3],     pah[1], pal[1]);
            split2h(sc[2 * kk + 1][0], sc[2 * kk + 1][1], pah[2], pal[2]);
            split2h(sc[2 * kk + 1][2], sc[2 * kk + 1][3], pah[3], pal[3]);

            const int vrow = 16 * kk + (lane & 15);
            const int vr7 = vrow & 7;
#pragma unroll
            for (int j = 0; j < 4; j++) {
                const uint32_t va = bb + 8192 + (uint32_t)vrow * 128 +
                    (uint32_t)(((2 * j + (lane >> 4)) ^ vr7) << 4);
                uint32_t vhf[4];
                ldsm4t(vhf, va);
                mma16816h(oac[2 * j],     pah, vhf + 0);
                mma16816h(oac[2 * j + 1], pah, vhf + 2);
                mma16816h(oac[2 * j],     pal, vhf + 0);
                mma16816h(oac[2 * j + 1], pal, vhf + 2);
            }
        }
    }

    // ---- epilogue: ctx fp16 hi/lo ----
    const int bb_ = bh >> 4, hh = bh & 15;
#pragma unroll
    for (int h = 0; h < 2; h++) {
        const float invl = 1.f / l_i[h];
        const int rg = qbase + rb + (lane >> 2) + 8 * h;
        const size_t mrow = (size_t)(bb_ * 2048 + rg) * 1024;
#pragma unroll
        for (int t = 0; t < 8; t++) {
            const float v0 = oac[t][2 * h] * invl;
            const float v1 = oac[t][2 * h + 1] * invl;
            const int col = hh * 64 + t * 8 + 2 * (lane & 3);
            uint32_t hi, lo;
            split2h(v0, v1, hi, lo);
            *(uint32_t*)(Ohi + mrow + col) = hi;
            *(uint32_t*)(Olo + mrow + col) = lo;
        }
    }
}

// ---------------------------------------------------------------------------
extern "C" void kernel_launch(void* const* d_in, const int* in_sizes, int n_in,
                              void* d_out, int out_size)
{
    const float* x  = (const float*)d_in[0];
    const float* Wq = (const float*)d_in[2];
    const float* bq = (const float*)d_in[3];
    const float* Wk = (const float*)d_in[4];
    const float* bk = (const float*)d_in[5];
    const float* Wv = (const float*)d_in[6];
    const float* bv = (const float*)d_in[7];
    const float* Wo = (const float*)d_in[8];
    const float* bo = (const float*)d_in[9];

    __half *xh, *xl, *wth, *qh, *ql, *kh, *vh;
    cudaGetSymbolAddress((void**)&xh, g_Xhi);
    cudaGetSymbolAddress((void**)&xl, g_Xlo);
    cudaGetSymbolAddress((void**)&wth, g_Wth);
    cudaGetSymbolAddress((void**)&qh, g_Qh);
    cudaGetSymbolAddress((void**)&ql, g_Ql);
    cudaGetSymbolAddress((void**)&kh, g_Kh);
    cudaGetSymbolAddress((void**)&vh, g_Vh);

    const int n4 = M_ROWS * D_ / 4;
    const dim3 tb(32, 32);

    cudaFuncSetAttribute(gemm_tc, cudaFuncAttributeMaxDynamicSharedMemorySize, GSMEM);
    cudaFuncSetAttribute(flash_attn_tc, cudaFuncAttributeMaxDynamicSharedMemorySize, ASMEM);

    split_f16<<<(n4 + 255) / 256, 256>>>(x, xh, xl, n4);
    transpose_f16<<<dim3(32, 32, 4), tb>>>(Wq, Wk, Wv, Wo, wth);

    gemm_tc<<<dim3(24, 32), 256, GSMEM>>>(xh, xl, wth, bq, bk, bv,
                                          nullptr, qh, ql, kh, vh, 1);

    flash_attn_tc<<<dim3(32, BH_), 128, ASMEM>>>(qh, ql, kh, vh, xh, xl);

    gemm_tc<<<dim3(8, 32), 256, GSMEM>>>(xh, xl, wth + 3 * D_ * D_,
                                         bo, bo, bo, (float*)d_out,
                                         nullptr, nullptr, nullptr, nullptr, 0);
}

// round 15
// speedup vs baseline: 1.4652x; 1.1338x over previous
#include <cuda_runtime.h>
#include <cuda_bf16.h>
#include <cuda_fp16.h>
#include <cstdint>

#define B_   2
#define S_   2048
#define D_   1024
#define H_   16
#define DK_  64
#define BH_  (B_ * H_)
#define M_ROWS (B_ * S_)   // 4096

#define QSCALE 0.18033688011112042f   // log2(e)/sqrt(64)

// ---------------- scratch ----------------
__device__ __half g_Xhi[M_ROWS * D_];
__device__ __half g_Xlo[M_ROWS * D_];
__device__ __half g_Wth[4 * D_ * D_];
__device__ __half g_Qh[BH_ * S_ * DK_];
__device__ __half g_Ql[BH_ * S_ * DK_];
__device__ __half g_Kh[BH_ * S_ * DK_];
__device__ __half g_Vh[BH_ * S_ * DK_];

// ---------------- helpers ----------------
__device__ __forceinline__ uint32_t smem_u32(const void* p) {
    uint32_t a;
    asm("{ .reg .u64 t; cvta.to.shared.u64 t, %1; cvt.u32.u64 %0, t; }" : "=r"(a) : "l"(p));
    return a;
}
__device__ __forceinline__ void ldsm4(uint32_t* r, uint32_t addr) {
    asm volatile("ldmatrix.sync.aligned.m8n8.x4.shared.b16 {%0,%1,%2,%3}, [%4];"
        : "=r"(r[0]), "=r"(r[1]), "=r"(r[2]), "=r"(r[3]) : "r"(addr));
}
__device__ __forceinline__ void ldsm4t(uint32_t* r, uint32_t addr) {
    asm volatile("ldmatrix.sync.aligned.m8n8.x4.trans.shared.b16 {%0,%1,%2,%3}, [%4];"
        : "=r"(r[0]), "=r"(r[1]), "=r"(r[2]), "=r"(r[3]) : "r"(addr));
}
// fp16 x fp16 -> fp32
__device__ __forceinline__ void mma16816h(float* c, const uint32_t* a, const uint32_t* b) {
    asm volatile("mma.sync.aligned.m16n8k16.row.col.f32.f16.f16.f32 "
        "{%0,%1,%2,%3}, {%4,%5,%6,%7}, {%8,%9}, {%0,%1,%2,%3};"
        : "+f"(c[0]), "+f"(c[1]), "+f"(c[2]), "+f"(c[3])
        : "r"(a[0]), "r"(a[1]), "r"(a[2]), "r"(a[3]), "r"(b[0]), "r"(b[1]));
}
// fp16 x fp16 -> fp16 (GEMM correction pass)
__device__ __forceinline__ void mma16816hh(uint32_t* c, const uint32_t* a, const uint32_t* b) {
    asm volatile("mma.sync.aligned.m16n8k16.row.col.f16.f16.f16.f16 "
        "{%0,%1}, {%2,%3,%4,%5}, {%6,%7}, {%0,%1};"
        : "+r"(c[0]), "+r"(c[1])
        : "r"(a[0]), "r"(a[1]), "r"(a[2]), "r"(a[3]), "r"(b[0]), "r"(b[1]));
}
__device__ __forceinline__ void cpa16(uint32_t d, const void* g) {
    asm volatile("cp.async.cg.shared.global [%0], [%1], 16;" :: "r"(d), "l"(g));
}
#define CP_COMMIT() asm volatile("cp.async.commit_group;" ::: "memory")
#define CP_WAIT0()  asm volatile("cp.async.wait_group 0;" ::: "memory")

__device__ __forceinline__ uint32_t f16pack(float a, float b) {
    uint32_t h;
    asm("cvt.rn.f16x2.f32 %0, %1, %2;" : "=r"(h) : "f"(b), "f"(a));
    return h;
}
__device__ __forceinline__ void split2h(float a, float b, uint32_t& hi, uint32_t& lo) {
    uint32_t h;
    asm("cvt.rn.f16x2.f32 %0, %1, %2;" : "=r"(h) : "f"(b), "f"(a));
    const __half2 hp = *(const __half2*)&h;
    const float fa = __half2float(__low2half(hp));
    const float fb = __half2float(__high2half(hp));
    const float ra = a - fa, rb = b - fb;
    uint32_t l;
    asm("cvt.rn.f16x2.f32 %0, %1, %2;" : "=r"(l) : "f"(rb), "f"(ra));
    hi = h; lo = l;
}

// ---------------------------------------------------------------------------
__global__ __launch_bounds__(256) void split_f16(
    const float* __restrict__ src, __half* __restrict__ hi,
    __half* __restrict__ lo, int n4)
{
    int i = blockIdx.x * blockDim.x + threadIdx.x;
    if (i >= n4) return;
    float4 v = ((const float4*)src)[i];
    uint32_t h0, l0, h1, l1;
    split2h(v.x, v.y, h0, l0);
    split2h(v.z, v.w, h1, l1);
    uint2 hu = {h0, h1}, lu = {l0, l1};
    ((uint2*)hi)[i] = hu;
    ((uint2*)lo)[i] = lu;
}

// ---------------------------------------------------------------------------
__global__ void transpose_f16(const float* __restrict__ W0,
                              const float* __restrict__ W1,
                              const float* __restrict__ W2,
                              const float* __restrict__ W3,
                              __half* __restrict__ hi)
{
    __shared__ float t[32][33];
    const float* W = (blockIdx.z == 0) ? W0 : (blockIdx.z == 1) ? W1 :
                     (blockIdx.z == 2) ? W2 : W3;
    const int k = blockIdx.y * 32 + threadIdx.y;
    const int n = blockIdx.x * 32 + threadIdx.x;
    t[threadIdx.y][threadIdx.x] = W[(size_t)k * D_ + n];
    __syncthreads();
    const int nn = blockIdx.x * 32 + threadIdx.y + blockIdx.z * D_;
    const int kk = blockIdx.y * 32 + threadIdx.x;
    hi[(size_t)nn * D_ + kk] = __float2half_rn(t[threadIdx.x][threadIdx.y]);
}

// ---------------------------------------------------------------------------
// HMMA GEMM, templated on TWOPASS:
//   TWOPASS=true : y = xh*wh (fp32 acc) + xl*wh (fp16 acc)   [QKV]
//   TWOPASS=false: y = xh*wh (fp32 acc)                       [out-proj]
// ---------------------------------------------------------------------------
#define GROWB 80
#define SLABB (128 * GROWB)       // 10240
#define STAGEB (3 * SLABB)        // 30720
#define GSMEM (2 * STAGEB)        // 61440

template <bool TWOPASS>
__global__ __launch_bounds__(256, 2) void gemm_tc(
    const __half* __restrict__ Ah, const __half* __restrict__ Al,
    const __half* __restrict__ Bh,
    const float* __restrict__ b0, const float* __restrict__ b1,
    const float* __restrict__ b2, float* __restrict__ Yf,
    __half* __restrict__ Qh, __half* __restrict__ Ql,
    __half* __restrict__ Kh, __half* __restrict__ Vh,
    int mode)
{
    extern __shared__ __align__(16) unsigned char dsm[];
    const uint32_t s0 = smem_u32(dsm);

    const int tid = threadIdx.x, wid = tid >> 5, lane = tid & 31;
    const int wm = wid >> 2, wn = wid & 3;
    const int bm = blockIdx.y * 128, bn = blockIdx.x * 128;

    const __half* gAh = Ah + (size_t)bm * 1024;
    const __half* gAl = Al + (size_t)bm * 1024;
    const __half* gBh = Bh + (size_t)bn * 1024;

    const uint32_t aRow = (uint32_t)(wm * 64 + (lane & 15));
    const uint32_t aCol = (uint32_t)(lane >> 4) * 16;
    const uint32_t bRow0 = (uint32_t)(wn * 32 + ((lane >> 4) & 1) * 8 + (lane & 7));
    const uint32_t bKoff = (uint32_t)((lane >> 3) & 1) * 16;

    float acc[16][4];
    uint32_t facc[16][2];
#pragma unroll
    for (int i = 0; i < 16; i++) {
#pragma unroll
        for (int j = 0; j < 4; j++) acc[i][j] = 0.f;
        facc[i][0] = 0u; facc[i][1] = 0u;
    }

    auto issue = [&](int ks) {
        const uint32_t st = s0 + (uint32_t)(ks & 1) * STAGEB;
#pragma unroll
        for (int p = 0; p < 6; p++) {
            const int id = p * 256 + tid;
            const int slab = id >> 9;
            if (!TWOPASS && slab == 1) continue;   // Al not needed
            const int within = id & 511;
            const int row = within >> 2, ch = within & 3;
            const __half* base = (slab == 0) ? gAh : (slab == 1) ? gAl : gBh;
            cpa16(st + (uint32_t)slab * SLABB + (uint32_t)row * GROWB + (uint32_t)ch * 16,
                  base + ks * 32 + (size_t)row * 1024 + ch * 8);
        }
        CP_COMMIT();
    };

    issue(0);

    for (int ks = 0; ks < 32; ks++) {
        CP_WAIT0();
        __syncthreads();
        if (ks + 1 < 32) issue(ks + 1);

        const uint32_t sb  = s0 + (uint32_t)(ks & 1) * STAGEB;
        const uint32_t SAh = sb, SAl = sb + SLABB, SBh = sb + 2 * SLABB;

#pragma unroll
        for (int h = 0; h < 2; h++) {
            uint32_t fA[4][4], fB[4][2];
            const uint32_t hoff = (uint32_t)h * 32;
#pragma unroll
            for (int mt = 0; mt < 4; mt++)
                ldsm4(fA[mt], SAh + (aRow + (uint32_t)(mt * 16)) * GROWB + hoff + aCol);
#pragma unroll
            for (int g = 0; g < 2; g++) {
                uint32_t r[4];
                ldsm4(r, SBh + (bRow0 + (uint32_t)(g * 16)) * GROWB + hoff + bKoff);
                fB[g * 2][0] = r[0]; fB[g * 2][1] = r[1];
                fB[g * 2 + 1][0] = r[2]; fB[g * 2 + 1][1] = r[3];
            }
#pragma unroll
            for (int mt = 0; mt < 4; mt++)
#pragma unroll
                for (int nt = 0; nt < 4; nt++)
                    mma16816h(acc[mt * 4 + nt], fA[mt], fB[nt]);
            if (TWOPASS) {
#pragma unroll
                for (int mt = 0; mt < 4; mt++)
                    ldsm4(fA[mt], SAl + (aRow + (uint32_t)(mt * 16)) * GROWB + hoff + aCol);
#pragma unroll
                for (int mt = 0; mt < 4; mt++)
#pragma unroll
                    for (int nt = 0; nt < 4; nt++)
                        mma16816hh(facc[mt * 4 + nt], fA[mt], fB[nt]);
            }
        }
    }

    // ---- epilogue ----
    const int qr = lane >> 2, qc = (lane & 3) * 2;
    const int proj = bn >> 10;
    const float* bias = (proj == 0) ? b0 : (proj == 1) ? b1 : b2;
    const float scale = (mode == 1 && proj == 0) ? QSCALE : 1.0f;
    const int bnl = bn & 1023;

#pragma unroll
    for (int mt = 0; mt < 4; mt++) {
#pragma unroll
        for (int nt = 0; nt < 4; nt++) {
            const int i = mt * 4 + nt;
            float v0f = acc[i][0], v1f = acc[i][1];
            float v2f = acc[i][2], v3f = acc[i][3];
            if (TWOPASS) {
                const __half2 c01 = *(const __half2*)&facc[i][0];
                const __half2 c23 = *(const __half2*)&facc[i][1];
                v0f += __half2float(__low2half(c01));
                v1f += __half2float(__high2half(c01));
                v2f += __half2float(__low2half(c23));
                v3f += __half2float(__high2half(c23));
            }
            const int r0 = bm + wm * 64 + mt * 16 + qr;
            const int cn = bnl + wn * 32 + nt * 8 + qc;
            const float bv0 = bias[cn], bv1 = bias[cn + 1];
            if (mode == 0) {
                float2 v0 = {v0f + bv0, v1f + bv1};
                float2 v1 = {v2f + bv0, v3f + bv1};
                *(float2*)(Yf + (size_t)r0 * 1024 + cn) = v0;
                *(float2*)(Yf + (size_t)(r0 + 8) * 1024 + cn) = v1;
            } else {
                const float w0 = (v0f + bv0) * scale, w1 = (v1f + bv1) * scale;
                const float w2 = (v2f + bv0) * scale, w3 = (v3f + bv1) * scale;
                const int h  = cn >> 6, dk = cn & 63;
                const int b0i = r0 >> 11, s0i = r0 & 2047;
                const int b1i = (r0 + 8) >> 11, s1i = (r0 + 8) & 2047;
                const size_t o0 = (((size_t)(b0i * H_ + h)) * S_ + s0i) * DK_ + dk;
                const size_t o1 = (((size_t)(b1i * H_ + h)) * S_ + s1i) * DK_ + dk;
                if (proj == 0) {
                    uint32_t h0, l0, h1, l1;
                    split2h(w0, w1, h0, l0);
                    split2h(w2, w3, h1, l1);
                    *(uint32_t*)(Qh + o0) = h0; *(uint32_t*)(Ql + o0) = l0;
                    *(uint32_t*)(Qh + o1) = h1; *(uint32_t*)(Ql + o1) = l1;
                } else {
                    __half* Y = (proj == 1) ? Kh : Vh;
                    *(uint32_t*)(Y + o0) = f16pack(w0, w1);
                    *(uint32_t*)(Y + o1) = f16pack(w2, w3);
                }
            }
        }
    }
}

// ---------------------------------------------------------------------------
// Flash attention (causal), fp16:
//   scores = (qh+ql) . kh   (2-pass, Q exact)
//   oac   += fp16(p) . vh   (1-pass; p rounding ~2^-12)
// 128 thr / 64 q-rows, 2 CTAs/SM. ctx written as fp16 hi only.
// smem: Qh@0, Ql@8192; stage st at 16384+st*16384: Kh+0, Vh+8192. 48K.
// ---------------------------------------------------------------------------
#define ASMEM 49152

__global__ __launch_bounds__(128, 2) void flash_attn_tc(
    const __half* __restrict__ Qh, const __half* __restrict__ Ql,
    const __half* __restrict__ Kh, const __half* __restrict__ Vh,
    __half* __restrict__ Ohi)
{
    extern __shared__ __align__(16) unsigned char sm[];
    const uint32_t s0 = smem_u32(sm);

    const int tid = threadIdx.x, wid = tid >> 5, lane = tid & 31;
    const int qt = 31 - blockIdx.x;
    const int bh = blockIdx.y;
    const int qbase = qt * 64;
    const int njt = qt + 1;
    const int rb = wid * 16;

    {
        const int arr = tid >> 6;
        const int t2 = tid & 63;
        const __half* base = (arr ? Ql : Qh) + ((size_t)bh * S_ + qbase) * DK_;
        const uint32_t db = (uint32_t)arr * 8192;
#pragma unroll
        for (int p = 0; p < 8; p++) {
            const int idx = p * 64 + t2;
            const int row = idx >> 3, ch = idx & 7;
            *(uint4*)(sm + db + (uint32_t)row * 128 + (uint32_t)((ch ^ (row & 7)) << 4)) =
                *(const uint4*)(base + (size_t)row * 64 + ch * 8);
        }
    }
    __syncthreads();

    uint32_t qfh[4][4], qfl[4][4];
    {
        const int row = rb + (lane & 15);
        const int r7 = row & 7;
#pragma unroll
        for (int kk = 0; kk < 4; kk++) {
            const uint32_t a = s0 + (uint32_t)row * 128 +
                (uint32_t)(((2 * kk + (lane >> 4)) ^ r7) << 4);
            ldsm4(qfh[kk], a);
            ldsm4(qfl[kk], a + 8192);
        }
    }
    __syncthreads();

    const int a2 = tid >> 6;
    const int t6 = tid & 63;
    const __half* kvsrc = (a2 == 0) ? Kh : Vh;
    kvsrc += (size_t)bh * S_ * DK_;
    const uint32_t kvdst = s0 + 16384 + (uint32_t)a2 * 8192;

    {
        const __half* g = kvsrc;
#pragma unroll
        for (int p = 0; p < 8; p++) {
            const int idx = p * 64 + t6;
            const int row = idx >> 3, ch = idx & 7;
            cpa16(kvdst + (uint32_t)row * 128 + (uint32_t)((ch ^ (row & 7)) << 4),
                  g + (size_t)row * 64 + ch * 8);
        }
    }
    CP_COMMIT();

    float m_i[2] = {-1e30f, -1e30f};
    float l_i[2] = {0.f, 0.f};
    float oac[8][4];
#pragma unroll
    for (int t = 0; t < 8; t++)
#pragma unroll
        for (int e = 0; e < 4; e++) oac[t][e] = 0.f;

    for (int jt = 0; jt < njt; jt++) {
        CP_WAIT0();
        __syncthreads();
        const uint32_t bb = s0 + 16384 + (uint32_t)(jt & 1) * 16384;

        if (jt + 1 < njt) {
            const __half* g = kvsrc + (size_t)(jt + 1) * 64 * 64;
            const uint32_t db = kvdst + (uint32_t)((jt + 1) & 1) * 16384;
#pragma unroll
            for (int p = 0; p < 8; p++) {
                const int idx = p * 64 + t6;
                const int row = idx >> 3, ch = idx & 7;
                cpa16(db + (uint32_t)row * 128 + (uint32_t)((ch ^ (row & 7)) << 4),
                      g + (size_t)row * 64 + ch * 8);
            }
            CP_COMMIT();
        }

        // ---- scores: (qh + ql) . kh ----
        float sc[8][4];
#pragma unroll
        for (int t = 0; t < 8; t++)
#pragma unroll
            for (int e = 0; e < 4; e++) sc[t][e] = 0.f;

#pragma unroll
        for (int kk = 0; kk < 4; kk++) {
#pragma unroll
            for (int j = 0; j < 4; j++) {
                const int krow = 16 * j + (lane & 7) + ((lane & 16) >> 1);
                const uint32_t ka = bb + (uint32_t)krow * 128 +
                    (uint32_t)(((2 * kk + ((lane >> 3) & 1)) ^ (krow & 7)) << 4);
                uint32_t khf[4];
                ldsm4(khf, ka);
                mma16816h(sc[2 * j],     qfh[kk], khf + 0);
                mma16816h(sc[2 * j + 1], qfh[kk], khf + 2);
                mma16816h(sc[2 * j],     qfl[kk], khf + 0);
                mma16816h(sc[2 * j + 1], qfl[kk], khf + 2);
            }
        }

        if (jt == njt - 1) {
#pragma unroll
            for (int t = 0; t < 8; t++)
#pragma unroll
                for (int e = 0; e < 4; e++) {
                    const int kg = t * 8 + 2 * (lane & 3) + (e & 1);
                    const int qg = rb + (lane >> 2) + (e >> 1) * 8;
                    if (kg > qg) sc[t][e] = -1e9f;
                }
        }

#pragma unroll
        for (int h = 0; h < 2; h++) {
            float mr = -1e30f;
#pragma unroll
            for (int t = 0; t < 8; t++)
                mr = fmaxf(mr, fmaxf(sc[t][2 * h], sc[t][2 * h + 1]));
            mr = fmaxf(mr, __shfl_xor_sync(0xffffffffu, mr, 1));
            mr = fmaxf(mr, __shfl_xor_sync(0xffffffffu, mr, 2));
            const float mn = fmaxf(m_i[h], mr);
            if (__any_sync(0xffffffffu, mn != m_i[h])) {
                const float alpha = exp2f(m_i[h] - mn);
                m_i[h] = mn;
                l_i[h] *= alpha;
#pragma unroll
                for (int t = 0; t < 8; t++) {
                    oac[t][2 * h]     *= alpha;
                    oac[t][2 * h + 1] *= alpha;
                }
            }
            float rs = 0.f;
#pragma unroll
            for (int t = 0; t < 8; t++) {
                sc[t][2 * h]     = exp2f(sc[t][2 * h] - mn);
                sc[t][2 * h + 1] = exp2f(sc[t][2 * h + 1] - mn);
                rs += sc[t][2 * h] + sc[t][2 * h + 1];
            }
            rs += __shfl_xor_sync(0xffffffffu, rs, 1);
            rs += __shfl_xor_sync(0xffffffffu, rs, 2);
            l_i[h] += rs;
        }

        // ---- PV: fp16(p) . vh (single pass) ----
#pragma unroll
        for (int kk = 0; kk < 4; kk++) {
            uint32_t pah[4];
            pah[0] = f16pack(sc[2 * kk][0],     sc[2 * kk][1]);
            pah[1] = f16pack(sc[2 * kk][2],     sc[2 * kk][3]);
            pah[2] = f16pack(sc[2 * kk + 1][0], sc[2 * kk + 1][1]);
            pah[3] = f16pack(sc[2 * kk + 1][2], sc[2 * kk + 1][3]);

            const int vrow = 16 * kk + (lane & 15);
            const int vr7 = vrow & 7;
#pragma unroll
            for (int j = 0; j < 4; j++) {
                const uint32_t va = bb + 8192 + (uint32_t)vrow * 128 +
                    (uint32_t)(((2 * j + (lane >> 4)) ^ vr7) << 4);
                uint32_t vhf[4];
                ldsm4t(vhf, va);
                mma16816h(oac[2 * j],     pah, vhf + 0);
                mma16816h(oac[2 * j + 1], pah, vhf + 2);
            }
        }
    }

    // ---- epilogue: ctx fp16 hi only ----
    const int bb_ = bh >> 4, hh = bh & 15;
#pragma unroll
    for (int h = 0; h < 2; h++) {
        const float invl = 1.f / l_i[h];
        const int rg = qbase + rb + (lane >> 2) + 8 * h;
        const size_t mrow = (size_t)(bb_ * 2048 + rg) * 1024;
#pragma unroll
        for (int t = 0; t < 8; t++) {
            const float v0 = oac[t][2 * h] * invl;
            const float v1 = oac[t][2 * h + 1] * invl;
            const int col = hh * 64 + t * 8 + 2 * (lane & 3);
            *(uint32_t*)(Ohi + mrow + col) = f16pack(v0, v1);
        }
    }
}

// ---------------------------------------------------------------------------
extern "C" void kernel_launch(void* const* d_in, const int* in_sizes, int n_in,
                              void* d_out, int out_size)
{
    const float* x  = (const float*)d_in[0];
    const float* Wq = (const float*)d_in[2];
    const float* bq = (const float*)d_in[3];
    const float* Wk = (const float*)d_in[4];
    const float* bk = (const float*)d_in[5];
    const float* Wv = (const float*)d_in[6];
    const float* bv = (const float*)d_in[7];
    const float* Wo = (const float*)d_in[8];
    const float* bo = (const float*)d_in[9];

    __half *xh, *xl, *wth, *qh, *ql, *kh, *vh;
    cudaGetSymbolAddress((void**)&xh, g_Xhi);
    cudaGetSymbolAddress((void**)&xl, g_Xlo);
    cudaGetSymbolAddress((void**)&wth, g_Wth);
    cudaGetSymbolAddress((void**)&qh, g_Qh);
    cudaGetSymbolAddress((void**)&ql, g_Ql);
    cudaGetSymbolAddress((void**)&kh, g_Kh);
    cudaGetSymbolAddress((void**)&vh, g_Vh);

    const int n4 = M_ROWS * D_ / 4;
    const dim3 tb(32, 32);

    cudaFuncSetAttribute(gemm_tc<true>, cudaFuncAttributeMaxDynamicSharedMemorySize, GSMEM);
    cudaFuncSetAttribute(gemm_tc<false>, cudaFuncAttributeMaxDynamicSharedMemorySize, GSMEM);
    cudaFuncSetAttribute(flash_attn_tc, cudaFuncAttributeMaxDynamicSharedMemorySize, ASMEM);

    split_f16<<<(n4 + 255) / 256, 256>>>(x, xh, xl, n4);
    transpose_f16<<<dim3(32, 32, 4), tb>>>(Wq, Wk, Wv, Wo, wth);

    gemm_tc<true><<<dim3(24, 32), 256, GSMEM>>>(xh, xl, wth, bq, bk, bv,
                                                nullptr, qh, ql, kh, vh, 1);

    // attention writes ctx (fp16 hi only) into xh
    flash_attn_tc<<<dim3(32, BH_), 128, ASMEM>>>(qh, ql, kh, vh, xh);

    gemm_tc<false><<<dim3(8, 32), 256, GSMEM>>>(xh, xh, wth + 3 * D_ * D_,
                                                bo, bo, bo, (float*)d_out,
                                                nullptr, nullptr, nullptr, nullptr, 0);
}

// round 16
// speedup vs baseline: 1.9264x; 1.3148x over previous
#include <cuda_runtime.h>
#include <cuda_fp16.h>
#include <cstdint>

#define B_   2
#define S_   2048
#define D_   1024
#define H_   16
#define DK_  64
#define BH_  (B_ * H_)
#define M_ROWS (B_ * S_)   // 4096

#define QSCALE 0.18033688011112042f   // log2(e)/sqrt(64)

// ---------------- scratch ----------------
__device__ __half g_Xhi[M_ROWS * D_];
__device__ __half g_Wth[4 * D_ * D_];
__device__ __half g_Qh[BH_ * S_ * DK_];
__device__ __half g_Ql[BH_ * S_ * DK_];
__device__ __half g_Kh[BH_ * S_ * DK_];
__device__ __half g_Vh[BH_ * S_ * DK_];

// ---------------- helpers ----------------
__device__ __forceinline__ uint32_t smem_u32(const void* p) {
    uint32_t a;
    asm("{ .reg .u64 t; cvta.to.shared.u64 t, %1; cvt.u32.u64 %0, t; }" : "=r"(a) : "l"(p));
    return a;
}
__device__ __forceinline__ void ldsm4(uint32_t* r, uint32_t addr) {
    asm volatile("ldmatrix.sync.aligned.m8n8.x4.shared.b16 {%0,%1,%2,%3}, [%4];"
        : "=r"(r[0]), "=r"(r[1]), "=r"(r[2]), "=r"(r[3]) : "r"(addr));
}
__device__ __forceinline__ void ldsm4t(uint32_t* r, uint32_t addr) {
    asm volatile("ldmatrix.sync.aligned.m8n8.x4.trans.shared.b16 {%0,%1,%2,%3}, [%4];"
        : "=r"(r[0]), "=r"(r[1]), "=r"(r[2]), "=r"(r[3]) : "r"(addr));
}
// fp16 x fp16 -> fp32
__device__ __forceinline__ void mma16816h(float* c, const uint32_t* a, const uint32_t* b) {
    asm volatile("mma.sync.aligned.m16n8k16.row.col.f32.f16.f16.f32 "
        "{%0,%1,%2,%3}, {%4,%5,%6,%7}, {%8,%9}, {%0,%1,%2,%3};"
        : "+f"(c[0]), "+f"(c[1]), "+f"(c[2]), "+f"(c[3])
        : "r"(a[0]), "r"(a[1]), "r"(a[2]), "r"(a[3]), "r"(b[0]), "r"(b[1]));
}
__device__ __forceinline__ void cpa16(uint32_t d, const void* g) {
    asm volatile("cp.async.cg.shared.global [%0], [%1], 16;" :: "r"(d), "l"(g));
}
#define CP_COMMIT() asm volatile("cp.async.commit_group;" ::: "memory")
#define CP_WAIT0()  asm volatile("cp.async.wait_group 0;" ::: "memory")

__device__ __forceinline__ uint32_t f16pack(float a, float b) {
    uint32_t h;
    asm("cvt.rn.f16x2.f32 %0, %1, %2;" : "=r"(h) : "f"(b), "f"(a));
    return h;
}
__device__ __forceinline__ void split2h(float a, float b, uint32_t& hi, uint32_t& lo) {
    uint32_t h;
    asm("cvt.rn.f16x2.f32 %0, %1, %2;" : "=r"(h) : "f"(b), "f"(a));
    const __half2 hp = *(const __half2*)&h;
    const float fa = __half2float(__low2half(hp));
    const float fb = __half2float(__high2half(hp));
    const float ra = a - fa, rb = b - fb;
    uint32_t l;
    asm("cvt.rn.f16x2.f32 %0, %1, %2;" : "=r"(l) : "f"(rb), "f"(ra));
    hi = h; lo = l;
}

// ---------------------------------------------------------------------------
// fp32 -> fp16 convert (hi only; correction term retired)
// ---------------------------------------------------------------------------
__global__ __launch_bounds__(256) void cvt_f16(
    const float* __restrict__ src, __half* __restrict__ hi, int n4)
{
    int i = blockIdx.x * blockDim.x + threadIdx.x;
    if (i >= n4) return;
    float4 v = ((const float4*)src)[i];
    uint2 hu;
    hu.x = f16pack(v.x, v.y);
    hu.y = f16pack(v.z, v.w);
    ((uint2*)hi)[i] = hu;
}

// ---------------------------------------------------------------------------
__global__ void transpose_f16(const float* __restrict__ W0,
                              const float* __restrict__ W1,
                              const float* __restrict__ W2,
                              const float* __restrict__ W3,
                              __half* __restrict__ hi)
{
    __shared__ float t[32][33];
    const float* W = (blockIdx.z == 0) ? W0 : (blockIdx.z == 1) ? W1 :
                     (blockIdx.z == 2) ? W2 : W3;
    const int k = blockIdx.y * 32 + threadIdx.y;
    const int n = blockIdx.x * 32 + threadIdx.x;
    t[threadIdx.y][threadIdx.x] = W[(size_t)k * D_ + n];
    __syncthreads();
    const int nn = blockIdx.x * 32 + threadIdx.y + blockIdx.z * D_;
    const int kk = blockIdx.y * 32 + threadIdx.x;
    hi[(size_t)nn * D_ + kk] = __float2half_rn(t[threadIdx.x][threadIdx.y]);
}

// ---------------------------------------------------------------------------
// HMMA GEMM, single pass: y = xh * wh (fp32 acc). 2 slabs/stage (A, B),
// 2-stage cp.async, 2 CTAs/SM.
// mode 1 epilogue: Q -> fp16 hi/lo (scaled); K,V -> fp16.
// ---------------------------------------------------------------------------
#define GROWB 80
#define SLABB (128 * GROWB)       // 10240
#define STAGEB (2 * SLABB)        // 20480
#define GSMEM (2 * STAGEB)        // 40960

__global__ __launch_bounds__(256, 2) void gemm_tc(
    const __half* __restrict__ Ah, const __half* __restrict__ Bh,
    const float* __restrict__ b0, const float* __restrict__ b1,
    const float* __restrict__ b2, float* __restrict__ Yf,
    __half* __restrict__ Qh, __half* __restrict__ Ql,
    __half* __restrict__ Kh, __half* __restrict__ Vh,
    int mode)
{
    extern __shared__ __align__(16) unsigned char dsm[];
    const uint32_t s0 = smem_u32(dsm);

    const int tid = threadIdx.x, wid = tid >> 5, lane = tid & 31;
    const int wm = wid >> 2, wn = wid & 3;
    const int bm = blockIdx.y * 128, bn = blockIdx.x * 128;

    const __half* gAh = Ah + (size_t)bm * 1024;
    const __half* gBh = Bh + (size_t)bn * 1024;

    const uint32_t aRow = (uint32_t)(wm * 64 + (lane & 15));
    const uint32_t aCol = (uint32_t)(lane >> 4) * 16;
    const uint32_t bRow0 = (uint32_t)(wn * 32 + ((lane >> 4) & 1) * 8 + (lane & 7));
    const uint32_t bKoff = (uint32_t)((lane >> 3) & 1) * 16;

    float acc[16][4];
#pragma unroll
    for (int i = 0; i < 16; i++)
#pragma unroll
        for (int j = 0; j < 4; j++) acc[i][j] = 0.f;

    // 4 chunks of 16B per thread: slab 0 = A, slab 1 = B
    auto issue = [&](int ks) {
        const uint32_t st = s0 + (uint32_t)(ks & 1) * STAGEB;
#pragma unroll
        for (int p = 0; p < 4; p++) {
            const int id = p * 256 + tid;
            const int slab = id >> 9;
            const int within = id & 511;
            const int row = within >> 2, ch = within & 3;
            const __half* base = (slab == 0) ? gAh : gBh;
            cpa16(st + (uint32_t)slab * SLABB + (uint32_t)row * GROWB + (uint32_t)ch * 16,
                  base + ks * 32 + (size_t)row * 1024 + ch * 8);
        }
        CP_COMMIT();
    };

    issue(0);

    for (int ks = 0; ks < 32; ks++) {
        CP_WAIT0();
        __syncthreads();
        if (ks + 1 < 32) issue(ks + 1);

        const uint32_t sb  = s0 + (uint32_t)(ks & 1) * STAGEB;
        const uint32_t SAh = sb, SBh = sb + SLABB;

#pragma unroll
        for (int h = 0; h < 2; h++) {
            uint32_t fA[4][4], fB[4][2];
            const uint32_t hoff = (uint32_t)h * 32;
#pragma unroll
            for (int mt = 0; mt < 4; mt++)
                ldsm4(fA[mt], SAh + (aRow + (uint32_t)(mt * 16)) * GROWB + hoff + aCol);
#pragma unroll
            for (int g = 0; g < 2; g++) {
                uint32_t r[4];
                ldsm4(r, SBh + (bRow0 + (uint32_t)(g * 16)) * GROWB + hoff + bKoff);
                fB[g * 2][0] = r[0]; fB[g * 2][1] = r[1];
                fB[g * 2 + 1][0] = r[2]; fB[g * 2 + 1][1] = r[3];
            }
#pragma unroll
            for (int mt = 0; mt < 4; mt++)
#pragma unroll
                for (int nt = 0; nt < 4; nt++)
                    mma16816h(acc[mt * 4 + nt], fA[mt], fB[nt]);
        }
    }

    // ---- epilogue ----
    const int qr = lane >> 2, qc = (lane & 3) * 2;
    const int proj = bn >> 10;
    const float* bias = (proj == 0) ? b0 : (proj == 1) ? b1 : b2;
    const float scale = (mode == 1 && proj == 0) ? QSCALE : 1.0f;
    const int bnl = bn & 1023;

#pragma unroll
    for (int mt = 0; mt < 4; mt++) {
#pragma unroll
        for (int nt = 0; nt < 4; nt++) {
            const int i = mt * 4 + nt;
            const float v0f = acc[i][0], v1f = acc[i][1];
            const float v2f = acc[i][2], v3f = acc[i][3];
            const int r0 = bm + wm * 64 + mt * 16 + qr;
            const int cn = bnl + wn * 32 + nt * 8 + qc;
            const float bv0 = bias[cn], bv1 = bias[cn + 1];
            if (mode == 0) {
                float2 v0 = {v0f + bv0, v1f + bv1};
                float2 v1 = {v2f + bv0, v3f + bv1};
                *(float2*)(Yf + (size_t)r0 * 1024 + cn) = v0;
                *(float2*)(Yf + (size_t)(r0 + 8) * 1024 + cn) = v1;
            } else {
                const float w0 = (v0f + bv0) * scale, w1 = (v1f + bv1) * scale;
                const float w2 = (v2f + bv0) * scale, w3 = (v3f + bv1) * scale;
                const int h  = cn >> 6, dk = cn & 63;
                const int b0i = r0 >> 11, s0i = r0 & 2047;
                const int b1i = (r0 + 8) >> 11, s1i = (r0 + 8) & 2047;
                const size_t o0 = (((size_t)(b0i * H_ + h)) * S_ + s0i) * DK_ + dk;
                const size_t o1 = (((size_t)(b1i * H_ + h)) * S_ + s1i) * DK_ + dk;
                if (proj == 0) {
                    uint32_t h0, l0, h1, l1;
                    split2h(w0, w1, h0, l0);
                    split2h(w2, w3, h1, l1);
                    *(uint32_t*)(Qh + o0) = h0; *(uint32_t*)(Ql + o0) = l0;
                    *(uint32_t*)(Qh + o1) = h1; *(uint32_t*)(Ql + o1) = l1;
                } else {
                    __half* Y = (proj == 1) ? Kh : Vh;
                    *(uint32_t*)(Y + o0) = f16pack(w0, w1);
                    *(uint32_t*)(Y + o1) = f16pack(w2, w3);
                }
            }
        }
    }
}

// ---------------------------------------------------------------------------
// Flash attention (causal), fp16 — unchanged from R15:
//   scores = (qh+ql) . kh   (2-pass, Q exact)
//   oac   += fp16(p) . vh   (1-pass)
// 128 thr / 64 q-rows, 2 CTAs/SM. ctx written fp16 hi only.
// ---------------------------------------------------------------------------
#define ASMEM 49152

__global__ __launch_bounds__(128, 2) void flash_attn_tc(
    const __half* __restrict__ Qh, const __half* __restrict__ Ql,
    const __half* __restrict__ Kh, const __half* __restrict__ Vh,
    __half* __restrict__ Ohi)
{
    extern __shared__ __align__(16) unsigned char sm[];
    const uint32_t s0 = smem_u32(sm);

    const int tid = threadIdx.x, wid = tid >> 5, lane = tid & 31;
    const int qt = 31 - blockIdx.x;
    const int bh = blockIdx.y;
    const int qbase = qt * 64;
    const int njt = qt + 1;
    const int rb = wid * 16;

    {
        const int arr = tid >> 6;
        const int t2 = tid & 63;
        const __half* base = (arr ? Ql : Qh) + ((size_t)bh * S_ + qbase) * DK_;
        const uint32_t db = (uint32_t)arr * 8192;
#pragma unroll
        for (int p = 0; p < 8; p++) {
            const int idx = p * 64 + t2;
            const int row = idx >> 3, ch = idx & 7;
            *(uint4*)(sm + db + (uint32_t)row * 128 + (uint32_t)((ch ^ (row & 7)) << 4)) =
                *(const uint4*)(base + (size_t)row * 64 + ch * 8);
        }
    }
    __syncthreads();

    uint32_t qfh[4][4], qfl[4][4];
    {
        const int row = rb + (lane & 15);
        const int r7 = row & 7;
#pragma unroll
        for (int kk = 0; kk < 4; kk++) {
            const uint32_t a = s0 + (uint32_t)row * 128 +
                (uint32_t)(((2 * kk + (lane >> 4)) ^ r7) << 4);
            ldsm4(qfh[kk], a);
            ldsm4(qfl[kk], a + 8192);
        }
    }
    __syncthreads();

    const int a2 = tid >> 6;
    const int t6 = tid & 63;
    const __half* kvsrc = (a2 == 0) ? Kh : Vh;
    kvsrc += (size_t)bh * S_ * DK_;
    const uint32_t kvdst = s0 + 16384 + (uint32_t)a2 * 8192;

    {
        const __half* g = kvsrc;
#pragma unroll
        for (int p = 0; p < 8; p++) {
            const int idx = p * 64 + t6;
            const int row = idx >> 3, ch = idx & 7;
            cpa16(kvdst + (uint32_t)row * 128 + (uint32_t)((ch ^ (row & 7)) << 4),
                  g + (size_t)row * 64 + ch * 8);
        }
    }
    CP_COMMIT();

    float m_i[2] = {-1e30f, -1e30f};
    float l_i[2] = {0.f, 0.f};
    float oac[8][4];
#pragma unroll
    for (int t = 0; t < 8; t++)
#pragma unroll
        for (int e = 0; e < 4; e++) oac[t][e] = 0.f;

    for (int jt = 0; jt < njt; jt++) {
        CP_WAIT0();
        __syncthreads();
        const uint32_t bb = s0 + 16384 + (uint32_t)(jt & 1) * 16384;

        if (jt + 1 < njt) {
            const __half* g = kvsrc + (size_t)(jt + 1) * 64 * 64;
            const uint32_t db = kvdst + (uint32_t)((jt + 1) & 1) * 16384;
#pragma unroll
            for (int p = 0; p < 8; p++) {
                const int idx = p * 64 + t6;
                const int row = idx >> 3, ch = idx & 7;
                cpa16(db + (uint32_t)row * 128 + (uint32_t)((ch ^ (row & 7)) << 4),
                      g + (size_t)row * 64 + ch * 8);
            }
            CP_COMMIT();
        }

        float sc[8][4];
#pragma unroll
        for (int t = 0; t < 8; t++)
#pragma unroll
            for (int e = 0; e < 4; e++) sc[t][e] = 0.f;

#pragma unroll
        for (int kk = 0; kk < 4; kk++) {
#pragma unroll
            for (int j = 0; j < 4; j++) {
                const int krow = 16 * j + (lane & 7) + ((lane & 16) >> 1);
                const uint32_t ka = bb + (uint32_t)krow * 128 +
                    (uint32_t)(((2 * kk + ((lane >> 3) & 1)) ^ (krow & 7)) << 4);
                uint32_t khf[4];
                ldsm4(khf, ka);
                mma16816h(sc[2 * j],     qfh[kk], khf + 0);
                mma16816h(sc[2 * j + 1], qfh[kk], khf + 2);
                mma16816h(sc[2 * j],     qfl[kk], khf + 0);
                mma16816h(sc[2 * j + 1], qfl[kk], khf + 2);
            }
        }

        if (jt == njt - 1) {
#pragma unroll
            for (int t = 0; t < 8; t++)
#pragma unroll
                for (int e = 0; e < 4; e++) {
                    const int kg = t * 8 + 2 * (lane & 3) + (e & 1);
                    const int qg = rb + (lane >> 2) + (e >> 1) * 8;
                    if (kg > qg) sc[t][e] = -1e9f;
                }
        }

#pragma unroll
        for (int h = 0; h < 2; h++) {
            float mr = -1e30f;
#pragma unroll
            for (int t = 0; t < 8; t++)
                mr = fmaxf(mr, fmaxf(sc[t][2 * h], sc[t][2 * h + 1]));
            mr = fmaxf(mr, __shfl_xor_sync(0xffffffffu, mr, 1));
            mr = fmaxf(mr, __shfl_xor_sync(0xffffffffu, mr, 2));
            const float mn = fmaxf(m_i[h], mr);
            if (__any_sync(0xffffffffu, mn != m_i[h])) {
                const float alpha = exp2f(m_i[h] - mn);
                m_i[h] = mn;
                l_i[h] *= alpha;
#pragma unroll
                for (int t = 0; t < 8; t++) {
                    oac[t][2 * h]     *= alpha;
                    oac[t][2 * h + 1] *= alpha;
                }
            }
            float rs = 0.f;
#pragma unroll
            for (int t = 0; t < 8; t++) {
                sc[t][2 * h]     = exp2f(sc[t][2 * h] - mn);
                sc[t][2 * h + 1] = exp2f(sc[t][2 * h + 1] - mn);
                rs += sc[t][2 * h] + sc[t][2 * h + 1];
            }
            rs += __shfl_xor_sync(0xffffffffu, rs, 1);
            rs += __shfl_xor_sync(0xffffffffu, rs, 2);
            l_i[h] += rs;
        }

#pragma unroll
        for (int kk = 0; kk < 4; kk++) {
            uint32_t pah[4];
            pah[0] = f16pack(sc[2 * kk][0],     sc[2 * kk][1]);
            pah[1] = f16pack(sc[2 * kk][2],     sc[2 * kk][3]);
            pah[2] = f16pack(sc[2 * kk + 1][0], sc[2 * kk + 1][1]);
            pah[3] = f16pack(sc[2 * kk + 1][2], sc[2 * kk + 1][3]);

            const int vrow = 16 * kk + (lane & 15);
            const int vr7 = vrow & 7;
#pragma unroll
            for (int j = 0; j < 4; j++) {
                const uint32_t va = bb + 8192 + (uint32_t)vrow * 128 +
                    (uint32_t)(((2 * j + (lane >> 4)) ^ vr7) << 4);
                uint32_t vhf[4];
                ldsm4t(vhf, va);
                mma16816h(oac[2 * j],     pah, vhf + 0);
                mma16816h(oac[2 * j + 1], pah, vhf + 2);
            }
        }
    }

    const int bb_ = bh >> 4, hh = bh & 15;
#pragma unroll
    for (int h = 0; h < 2; h++) {
        const float invl = 1.f / l_i[h];
        const int rg = qbase + rb + (lane >> 2) + 8 * h;
        const size_t mrow = (size_t)(bb_ * 2048 + rg) * 1024;
#pragma unroll
        for (int t = 0; t < 8; t++) {
            const float v0 = oac[t][2 * h] * invl;
            const float v1 = oac[t][2 * h + 1] * invl;
            const int col = hh * 64 + t * 8 + 2 * (lane & 3);
            *(uint32_t*)(Ohi + mrow + col) = f16pack(v0, v1);
        }
    }
}

// ---------------------------------------------------------------------------
extern "C" void kernel_launch(void* const* d_in, const int* in_sizes, int n_in,
                              void* d_out, int out_size)
{
    const float* x  = (const float*)d_in[0];
    const float* Wq = (const float*)d_in[2];
    const float* bq = (const float*)d_in[3];
    const float* Wk = (const float*)d_in[4];
    const float* bk = (const float*)d_in[5];
    const float* Wv = (const float*)d_in[6];
    const float* bv = (const float*)d_in[7];
    const float* Wo = (const float*)d_in[8];
    const float* bo = (const float*)d_in[9];

    __half *xh, *wth, *qh, *ql, *kh, *vh;
    cudaGetSymbolAddress((void**)&xh, g_Xhi);
    cudaGetSymbolAddress((void**)&wth, g_Wth);
    cudaGetSymbolAddress((void**)&qh, g_Qh);
    cudaGetSymbolAddress((void**)&ql, g_Ql);
    cudaGetSymbolAddress((void**)&kh, g_Kh);
    cudaGetSymbolAddress((void**)&vh, g_Vh);

    const int n4 = M_ROWS * D_ / 4;
    const dim3 tb(32, 32);

    cudaFuncSetAttribute(gemm_tc, cudaFuncAttributeMaxDynamicSharedMemorySize, GSMEM);
    cudaFuncSetAttribute(flash_attn_tc, cudaFuncAttributeMaxDynamicSharedMemorySize, ASMEM);

    cvt_f16<<<(n4 + 255) / 256, 256>>>(x, xh, n4);
    transpose_f16<<<dim3(32, 32, 4), tb>>>(Wq, Wk, Wv, Wo, wth);

    gemm_tc<<<dim3(24, 32), 256, GSMEM>>>(xh, wth, bq, bk, bv,
                                          nullptr, qh, ql, kh, vh, 1);

    // attention writes ctx (fp16) into xh
    flash_attn_tc<<<dim3(32, BH_), 128, ASMEM>>>(qh, ql, kh, vh, xh);

    gemm_tc<<<dim3(8, 32), 256, GSMEM>>>(xh, wth + 3 * D_ * D_,
                                         bo, bo, bo, (float*)d_out,
                                         nullptr, nullptr, nullptr, nullptr, 0);
}

// round 17
// speedup vs baseline: 2.0876x; 1.0837x over previous
#include <cuda_runtime.h>
#include <cuda_fp16.h>
#include <cstdint>

#define B_   2
#define S_   2048
#define D_   1024
#define H_   16
#define DK_  64
#define BH_  (B_ * H_)
#define M_ROWS (B_ * S_)   // 4096

#define QSCALE 0.18033688011112042f   // log2(e)/sqrt(64)

// ---------------- scratch ----------------
__device__ __half g_Xhi[M_ROWS * D_];
__device__ __half g_Wth[4 * D_ * D_];
__device__ __half g_Qh[BH_ * S_ * DK_];
__device__ __half g_Kh[BH_ * S_ * DK_];
__device__ __half g_Vh[BH_ * S_ * DK_];

// ---------------- helpers ----------------
__device__ __forceinline__ uint32_t smem_u32(const void* p) {
    uint32_t a;
    asm("{ .reg .u64 t; cvta.to.shared.u64 t, %1; cvt.u32.u64 %0, t; }" : "=r"(a) : "l"(p));
    return a;
}
__device__ __forceinline__ void ldsm4(uint32_t* r, uint32_t addr) {
    asm volatile("ldmatrix.sync.aligned.m8n8.x4.shared.b16 {%0,%1,%2,%3}, [%4];"
        : "=r"(r[0]), "=r"(r[1]), "=r"(r[2]), "=r"(r[3]) : "r"(addr));
}
__device__ __forceinline__ void ldsm4t(uint32_t* r, uint32_t addr) {
    asm volatile("ldmatrix.sync.aligned.m8n8.x4.trans.shared.b16 {%0,%1,%2,%3}, [%4];"
        : "=r"(r[0]), "=r"(r[1]), "=r"(r[2]), "=r"(r[3]) : "r"(addr));
}
// fp16 x fp16 -> fp32
__device__ __forceinline__ void mma16816h(float* c, const uint32_t* a, const uint32_t* b) {
    asm volatile("mma.sync.aligned.m16n8k16.row.col.f32.f16.f16.f32 "
        "{%0,%1,%2,%3}, {%4,%5,%6,%7}, {%8,%9}, {%0,%1,%2,%3};"
        : "+f"(c[0]), "+f"(c[1]), "+f"(c[2]), "+f"(c[3])
        : "r"(a[0]), "r"(a[1]), "r"(a[2]), "r"(a[3]), "r"(b[0]), "r"(b[1]));
}
__device__ __forceinline__ void cpa16(uint32_t d, const void* g) {
    asm volatile("cp.async.cg.shared.global [%0], [%1], 16;" :: "r"(d), "l"(g));
}
#define CP_COMMIT() asm volatile("cp.async.commit_group;" ::: "memory")
#define CP_WAIT0()  asm volatile("cp.async.wait_group 0;" ::: "memory")

__device__ __forceinline__ uint32_t f16pack(float a, float b) {
    uint32_t h;
    asm("cvt.rn.f16x2.f32 %0, %1, %2;" : "=r"(h) : "f"(b), "f"(a));
    return h;
}

// ---------------------------------------------------------------------------
// fp32 -> fp16 convert
// ---------------------------------------------------------------------------
__global__ __launch_bounds__(256) void cvt_f16(
    const float* __restrict__ src, __half* __restrict__ hi, int n4)
{
    int i = blockIdx.x * blockDim.x + threadIdx.x;
    if (i >= n4) return;
    float4 v = ((const float4*)src)[i];
    uint2 hu;
    hu.x = f16pack(v.x, v.y);
    hu.y = f16pack(v.z, v.w);
    ((uint2*)hi)[i] = hu;
}

// ---------------------------------------------------------------------------
__global__ void transpose_f16(const float* __restrict__ W0,
                              const float* __restrict__ W1,
                              const float* __restrict__ W2,
                              const float* __restrict__ W3,
                              __half* __restrict__ hi)
{
    __shared__ float t[32][33];
    const float* W = (blockIdx.z == 0) ? W0 : (blockIdx.z == 1) ? W1 :
                     (blockIdx.z == 2) ? W2 : W3;
    const int k = blockIdx.y * 32 + threadIdx.y;
    const int n = blockIdx.x * 32 + threadIdx.x;
    t[threadIdx.y][threadIdx.x] = W[(size_t)k * D_ + n];
    __syncthreads();
    const int nn = blockIdx.x * 32 + threadIdx.y + blockIdx.z * D_;
    const int kk = blockIdx.y * 32 + threadIdx.x;
    hi[(size_t)nn * D_ + kk] = __float2half_rn(t[threadIdx.x][threadIdx.y]);
}

// ---------------------------------------------------------------------------
// HMMA GEMM, single pass: y = xh * wh (fp32 acc). 2 slabs/stage,
// 2-stage cp.async, 2 CTAs/SM.
// mode 1: scatter Q/K/V as fp16 (Q scaled).
// ---------------------------------------------------------------------------
#define GROWB 80
#define SLABB (128 * GROWB)       // 10240
#define STAGEB (2 * SLABB)        // 20480
#define GSMEM (2 * STAGEB)        // 40960

__global__ __launch_bounds__(256, 2) void gemm_tc(
    const __half* __restrict__ Ah, const __half* __restrict__ Bh,
    const float* __restrict__ b0, const float* __restrict__ b1,
    const float* __restrict__ b2, float* __restrict__ Yf,
    __half* __restrict__ Qh, __half* __restrict__ Kh, __half* __restrict__ Vh,
    int mode)
{
    extern __shared__ __align__(16) unsigned char dsm[];
    const uint32_t s0 = smem_u32(dsm);

    const int tid = threadIdx.x, wid = tid >> 5, lane = tid & 31;
    const int wm = wid >> 2, wn = wid & 3;
    const int bm = blockIdx.y * 128, bn = blockIdx.x * 128;

    const __half* gAh = Ah + (size_t)bm * 1024;
    const __half* gBh = Bh + (size_t)bn * 1024;

    const uint32_t aRow = (uint32_t)(wm * 64 + (lane & 15));
    const uint32_t aCol = (uint32_t)(lane >> 4) * 16;
    const uint32_t bRow0 = (uint32_t)(wn * 32 + ((lane >> 4) & 1) * 8 + (lane & 7));
    const uint32_t bKoff = (uint32_t)((lane >> 3) & 1) * 16;

    float acc[16][4];
#pragma unroll
    for (int i = 0; i < 16; i++)
#pragma unroll
        for (int j = 0; j < 4; j++) acc[i][j] = 0.f;

    auto issue = [&](int ks) {
        const uint32_t st = s0 + (uint32_t)(ks & 1) * STAGEB;
#pragma unroll
        for (int p = 0; p < 4; p++) {
            const int id = p * 256 + tid;
            const int slab = id >> 9;
            const int within = id & 511;
            const int row = within >> 2, ch = within & 3;
            const __half* base = (slab == 0) ? gAh : gBh;
            cpa16(st + (uint32_t)slab * SLABB + (uint32_t)row * GROWB + (uint32_t)ch * 16,
                  base + ks * 32 + (size_t)row * 1024 + ch * 8);
        }
        CP_COMMIT();
    };

    issue(0);

    for (int ks = 0; ks < 32; ks++) {
        CP_WAIT0();
        __syncthreads();
        if (ks + 1 < 32) issue(ks + 1);

        const uint32_t sb  = s0 + (uint32_t)(ks & 1) * STAGEB;
        const uint32_t SAh = sb, SBh = sb + SLABB;

#pragma unroll
        for (int h = 0; h < 2; h++) {
            uint32_t fA[4][4], fB[4][2];
            const uint32_t hoff = (uint32_t)h * 32;
#pragma unroll
            for (int mt = 0; mt < 4; mt++)
                ldsm4(fA[mt], SAh + (aRow + (uint32_t)(mt * 16)) * GROWB + hoff + aCol);
#pragma unroll
            for (int g = 0; g < 2; g++) {
                uint32_t r[4];
                ldsm4(r, SBh + (bRow0 + (uint32_t)(g * 16)) * GROWB + hoff + bKoff);
                fB[g * 2][0] = r[0]; fB[g * 2][1] = r[1];
                fB[g * 2 + 1][0] = r[2]; fB[g * 2 + 1][1] = r[3];
            }
#pragma unroll
            for (int mt = 0; mt < 4; mt++)
#pragma unroll
                for (int nt = 0; nt < 4; nt++)
                    mma16816h(acc[mt * 4 + nt], fA[mt], fB[nt]);
        }
    }

    // ---- epilogue ----
    const int qr = lane >> 2, qc = (lane & 3) * 2;
    const int proj = bn >> 10;
    const float* bias = (proj == 0) ? b0 : (proj == 1) ? b1 : b2;
    const float scale = (mode == 1 && proj == 0) ? QSCALE : 1.0f;
    __half* Yv = (proj == 0) ? Qh : (proj == 1) ? Kh : Vh;
    const int bnl = bn & 1023;

#pragma unroll
    for (int mt = 0; mt < 4; mt++) {
#pragma unroll
        for (int nt = 0; nt < 4; nt++) {
            const int i = mt * 4 + nt;
            const float v0f = acc[i][0], v1f = acc[i][1];
            const float v2f = acc[i][2], v3f = acc[i][3];
            const int r0 = bm + wm * 64 + mt * 16 + qr;
            const int cn = bnl + wn * 32 + nt * 8 + qc;
            const float bv0 = bias[cn], bv1 = bias[cn + 1];
            if (mode == 0) {
                float2 v0 = {v0f + bv0, v1f + bv1};
                float2 v1 = {v2f + bv0, v3f + bv1};
                *(float2*)(Yf + (size_t)r0 * 1024 + cn) = v0;
                *(float2*)(Yf + (size_t)(r0 + 8) * 1024 + cn) = v1;
            } else {
                const float w0 = (v0f + bv0) * scale, w1 = (v1f + bv1) * scale;
                const float w2 = (v2f + bv0) * scale, w3 = (v3f + bv1) * scale;
                const int h  = cn >> 6, dk = cn & 63;
                const int b0i = r0 >> 11, s0i = r0 & 2047;
                const int b1i = (r0 + 8) >> 11, s1i = (r0 + 8) & 2047;
                const size_t o0 = (((size_t)(b0i * H_ + h)) * S_ + s0i) * DK_ + dk;
                const size_t o1 = (((size_t)(b1i * H_ + h)) * S_ + s1i) * DK_ + dk;
                *(uint32_t*)(Yv + o0) = f16pack(w0, w1);
                *(uint32_t*)(Yv + o1) = f16pack(w2, w3);
            }
        }
    }
}

// ---------------------------------------------------------------------------
// Flash attention (causal), fp16 single-pass both GEMMs:
//   scores = qh . kh      (32 MMAs/tile)
//   oac   += fp16(p) . vh (32 MMAs/tile)
// 128 thr / 64 q-rows, 2 CTAs/SM.
// smem: Q@0 (8K); stage st at 8192+st*16384: Kh+0, Vh+8192. Total 40K.
// ---------------------------------------------------------------------------
#define ASMEM 40960

__global__ __launch_bounds__(128, 2) void flash_attn_tc(
    const __half* __restrict__ Qh, const __half* __restrict__ Kh,
    const __half* __restrict__ Vh, __half* __restrict__ Ohi)
{
    extern __shared__ __align__(16) unsigned char sm[];
    const uint32_t s0 = smem_u32(sm);

    const int tid = threadIdx.x, wid = tid >> 5, lane = tid & 31;
    const int qt = 31 - blockIdx.x;
    const int bh = blockIdx.y;
    const int qbase = qt * 64;
    const int njt = qt + 1;
    const int rb = wid * 16;

    // ---- stage Q (8K, fp16) ----
    {
        const __half* base = Qh + ((size_t)bh * S_ + qbase) * DK_;
#pragma unroll
        for (int p = 0; p < 4; p++) {
            const int idx = p * 128 + tid;
            const int row = idx >> 3, ch = idx & 7;
            *(uint4*)(sm + (uint32_t)row * 128 + (uint32_t)((ch ^ (row & 7)) << 4)) =
                *(const uint4*)(base + (size_t)row * 64 + ch * 8);
        }
    }
    __syncthreads();

    uint32_t qfh[4][4];
    {
        const int row = rb + (lane & 15);
        const int r7 = row & 7;
#pragma unroll
        for (int kk = 0; kk < 4; kk++) {
            const uint32_t a = s0 + (uint32_t)row * 128 +
                (uint32_t)(((2 * kk + (lane >> 4)) ^ r7) << 4);
            ldsm4(qfh[kk], a);
        }
    }
    __syncthreads();

    const int a2 = tid >> 6;
    const int t6 = tid & 63;
    const __half* kvsrc = (a2 == 0) ? Kh : Vh;
    kvsrc += (size_t)bh * S_ * DK_;
    const uint32_t kvdst = s0 + 8192 + (uint32_t)a2 * 8192;

    {
        const __half* g = kvsrc;
#pragma unroll
        for (int p = 0; p < 8; p++) {
            const int idx = p * 64 + t6;
            const int row = idx >> 3, ch = idx & 7;
            cpa16(kvdst + (uint32_t)row * 128 + (uint32_t)((ch ^ (row & 7)) << 4),
                  g + (size_t)row * 64 + ch * 8);
        }
    }
    CP_COMMIT();

    float m_i[2] = {-1e30f, -1e30f};
    float l_i[2] = {0.f, 0.f};
    float oac[8][4];
#pragma unroll
    for (int t = 0; t < 8; t++)
#pragma unroll
        for (int e = 0; e < 4; e++) oac[t][e] = 0.f;

    for (int jt = 0; jt < njt; jt++) {
        CP_WAIT0();
        __syncthreads();
        const uint32_t bb = s0 + 8192 + (uint32_t)(jt & 1) * 16384;

        if (jt + 1 < njt) {
            const __half* g = kvsrc + (size_t)(jt + 1) * 64 * 64;
            const uint32_t db = kvdst + (uint32_t)((jt + 1) & 1) * 16384;
#pragma unroll
            for (int p = 0; p < 8; p++) {
                const int idx = p * 64 + t6;
                const int row = idx >> 3, ch = idx & 7;
                cpa16(db + (uint32_t)row * 128 + (uint32_t)((ch ^ (row & 7)) << 4),
                      g + (size_t)row * 64 + ch * 8);
            }
            CP_COMMIT();
        }

        // ---- scores: qh . kh (single pass) ----
        float sc[8][4];
#pragma unroll
        for (int t = 0; t < 8; t++)
#pragma unroll
            for (int e = 0; e < 4; e++) sc[t][e] = 0.f;

#pragma unroll
        for (int kk = 0; kk < 4; kk++) {
#pragma unroll
            for (int j = 0; j < 4; j++) {
                const int krow = 16 * j + (lane & 7) + ((lane & 16) >> 1);
                const uint32_t ka = bb + (uint32_t)krow * 128 +
                    (uint32_t)(((2 * kk + ((lane >> 3) & 1)) ^ (krow & 7)) << 4);
                uint32_t khf[4];
                ldsm4(khf, ka);
                mma16816h(sc[2 * j],     qfh[kk], khf + 0);
                mma16816h(sc[2 * j + 1], qfh[kk], khf + 2);
            }
        }

        if (jt == njt - 1) {
#pragma unroll
            for (int t = 0; t < 8; t++)
#pragma unroll
                for (int e = 0; e < 4; e++) {
                    const int kg = t * 8 + 2 * (lane & 3) + (e & 1);
                    const int qg = rb + (lane >> 2) + (e >> 1) * 8;
                    if (kg > qg) sc[t][e] = -1e9f;
                }
        }

#pragma unroll
        for (int h = 0; h < 2; h++) {
            float mr = -1e30f;
#pragma unroll
            for (int t = 0; t < 8; t++)
                mr = fmaxf(mr, fmaxf(sc[t][2 * h], sc[t][2 * h + 1]));
            mr = fmaxf(mr, __shfl_xor_sync(0xffffffffu, mr, 1));
            mr = fmaxf(mr, __shfl_xor_sync(0xffffffffu, mr, 2));
            const float mn = fmaxf(m_i[h], mr);
            if (__any_sync(0xffffffffu, mn != m_i[h])) {
                const float alpha = exp2f(m_i[h] - mn);
                m_i[h] = mn;
                l_i[h] *= alpha;
#pragma unroll
                for (int t = 0; t < 8; t++) {
                    oac[t][2 * h]     *= alpha;
                    oac[t][2 * h + 1] *= alpha;
                }
            }
            float rs = 0.f;
#pragma unroll
            for (int t = 0; t < 8; t++) {
                sc[t][2 * h]     = exp2f(sc[t][2 * h] - mn);
                sc[t][2 * h + 1] = exp2f(sc[t][2 * h + 1] - mn);
                rs += sc[t][2 * h] + sc[t][2 * h + 1];
            }
            rs += __shfl_xor_sync(0xffffffffu, rs, 1);
            rs += __shfl_xor_sync(0xffffffffu, rs, 2);
            l_i[h] += rs;
        }

        // ---- PV: fp16(p) . vh (single pass) ----
#pragma unroll
        for (int kk = 0; kk < 4; kk++) {
            uint32_t pah[4];
            pah[0] = f16pack(sc[2 * kk][0],     sc[2 * kk][1]);
            pah[1] = f16pack(sc[2 * kk][2],     sc[2 * kk][3]);
            pah[2] = f16pack(sc[2 * kk + 1][0], sc[2 * kk + 1][1]);
            pah[3] = f16pack(sc[2 * kk + 1][2], sc[2 * kk + 1][3]);

            const int vrow = 16 * kk + (lane & 15);
            const int vr7 = vrow & 7;
#pragma unroll
            for (int j = 0; j < 4; j++) {
                const uint32_t va = bb + 8192 + (uint32_t)vrow * 128 +
                    (uint32_t)(((2 * j + (lane >> 4)) ^ vr7) << 4);
                uint32_t vhf[4];
                ldsm4t(vhf, va);
                mma16816h(oac[2 * j],     pah, vhf + 0);
                mma16816h(oac[2 * j + 1], pah, vhf + 2);
            }
        }
    }

    // ---- epilogue: ctx fp16 ----
    const int bb_ = bh >> 4, hh = bh & 15;
#pragma unroll
    for (int h = 0; h < 2; h++) {
        const float invl = 1.f / l_i[h];
        const int rg = qbase + rb + (lane >> 2) + 8 * h;
        const size_t mrow = (size_t)(bb_ * 2048 + rg) * 1024;
#pragma unroll
        for (int t = 0; t < 8; t++) {
            const float v0 = oac[t][2 * h] * invl;
            const float v1 = oac[t][2 * h + 1] * invl;
            const int col = hh * 64 + t * 8 + 2 * (lane & 3);
            *(uint32_t*)(Ohi + mrow + col) = f16pack(v0, v1);
        }
    }
}

// ---------------------------------------------------------------------------
extern "C" void kernel_launch(void* const* d_in, const int* in_sizes, int n_in,
                              void* d_out, int out_size)
{
    const float* x  = (const float*)d_in[0];
    const float* Wq = (const float*)d_in[2];
    const float* bq = (const float*)d_in[3];
    const float* Wk = (const float*)d_in[4];
    const float* bk = (const float*)d_in[5];
    const float* Wv = (const float*)d_in[6];
    const float* bv = (const float*)d_in[7];
    const float* Wo = (const float*)d_in[8];
    const float* bo = (const float*)d_in[9];

    __half *xh, *wth, *qh, *kh, *vh;
    cudaGetSymbolAddress((void**)&xh, g_Xhi);
    cudaGetSymbolAddress((void**)&wth, g_Wth);
    cudaGetSymbolAddress((void**)&qh, g_Qh);
    cudaGetSymbolAddress((void**)&kh, g_Kh);
    cudaGetSymbolAddress((void**)&vh, g_Vh);

    const int n4 = M_ROWS * D_ / 4;
    const dim3 tb(32, 32);

    cudaFuncSetAttribute(gemm_tc, cudaFuncAttributeMaxDynamicSharedMemorySize, GSMEM);
    cudaFuncSetAttribute(flash_attn_tc, cudaFuncAttributeMaxDynamicSharedMemorySize, ASMEM);

    cvt_f16<<<(n4 + 255) / 256, 256>>>(x, xh, n4);
    transpose_f16<<<dim3(32, 32, 4), tb>>>(Wq, Wk, Wv, Wo, wth);

    gemm_tc<<<dim3(24, 32), 256, GSMEM>>>(xh, wth, bq, bk, bv,
                                          nullptr, qh, kh, vh, 1);

    // attention writes ctx (fp16) into xh
    flash_attn_tc<<<dim3(32, BH_), 128, ASMEM>>>(qh, kh, vh, xh);

    gemm_tc<<<dim3(8, 32), 256, GSMEM>>>(xh, wth + 3 * D_ * D_,
                                         bo, bo, bo, (float*)d_out,
                                         nullptr, nullptr, nullptr, 0);
}